// round 3
// baseline (speedup 1.0000x reference)
#include <cuda_runtime.h>
#include <cuda_bf16.h>
#include <math_constants.h>
#include <cstdint>

// ---------------------------------------------------------------------------
// MHA Round 3: projections via mma.sync bf16 (split hi/lo, 3-pass),
// attention fp32 flash-style (unchanged from R1).
// NOTE: harness lowers through compute_103 PTX -> tcgen05 unavailable;
// mma.sync.m16n8k16.bf16 is the tensor-core path that compiles.
// ---------------------------------------------------------------------------

#define BATCH 4
#define SEQ   2048
#define DM    1024
#define NH    16
#define HD    64
#define MROWS (BATCH * SEQ)   // 8192
#define ATT_SCALE 0.125f

#define BM 128
#define BN 128
#define BK 32
#define NCH (DM / BK)         // 32 k-chunks

// smem (b32 words): per buffer Ah[2048] Al[2048] Bh[2048] Bl[2048]
#define OFF_AH 0
#define OFF_AL 2048
#define OFF_BH 4096
#define OFF_BL 6144
#define BUF_W  8192
#define GEMM_SMEM_BYTES (2 * BUF_W * 4)   // 65536

// ---- scratch (device globals: allocation-free) ----------------------------
__device__ float g_Q[MROWS * DM];
__device__ float g_K[MROWS * DM];
__device__ float g_V[MROWS * DM];
__device__ float g_A[MROWS * DM];

// ---- mma.sync wrapper -------------------------------------------------------
__device__ __forceinline__ void mma16816(float* d, const uint32_t* a, const uint32_t* b) {
    asm volatile(
        "mma.sync.aligned.m16n8k16.row.col.f32.bf16.bf16.f32 "
        "{%0,%1,%2,%3}, {%4,%5,%6,%7}, {%8,%9}, {%0,%1,%2,%3};\n"
        : "+f"(d[0]), "+f"(d[1]), "+f"(d[2]), "+f"(d[3])
        : "r"(a[0]), "r"(a[1]), "r"(a[2]), "r"(a[3]), "r"(b[0]), "r"(b[1]));
}

__device__ __forceinline__ uint32_t pack_bf2(__nv_bfloat16 a, __nv_bfloat16 b) {
    __nv_bfloat162 t = __halves2bfloat162(a, b);
    return *(uint32_t*)&t;
}
__device__ __forceinline__ void split2(float v, __nv_bfloat16& h, __nv_bfloat16& l) {
    h = __float2bfloat16(v);
    l = __float2bfloat16(v - __bfloat162float(h));
}

// ---- GEMM: C[8192,1024] = A[8192,1024] @ W[1024,1024], fragment-major smem -
__device__ __forceinline__ void gemm_body(const float* __restrict__ A,
                                          const float* __restrict__ W,
                                          float* __restrict__ C)
{
    extern __shared__ uint32_t sm4[];
    const int tid  = threadIdx.x;
    const int lane = tid & 31;
    const int wid  = tid >> 5;
    const int wm   = wid >> 2;          // 0..1  (M)
    const int wn   = wid & 3;           // 0..3  (N)
    const int bm = blockIdx.y, bn = blockIdx.x;

    const float* Ab = A + (size_t)bm * BM * DM;
    const float* Bb = W + (size_t)bn * BN;

    float acc[4][4][4];
#pragma unroll
    for (int i = 0; i < 4; i++)
#pragma unroll
        for (int j = 0; j < 4; j++)
#pragma unroll
            for (int r = 0; r < 4; r++) acc[i][j][r] = 0.f;

    float4 axr[4], bxr[4];

    auto gload = [&](int c) {
#pragma unroll
        for (int i = 0; i < 4; i++) {
            int f = tid + i * 256;
            axr[i] = *(const float4*)(Ab + (size_t)(f >> 3) * DM + c * BK + (f & 7) * 4);
            bxr[i] = *(const float4*)(Bb + (size_t)(c * BK + (f >> 5)) * DM + (f & 31) * 4);
        }
    };

    auto sstore = [&](int dbuf) {
        uint32_t* base = sm4 + dbuf * BUF_W;
#pragma unroll
        for (int i = 0; i < 4; i++) {
            int f = tid + i * 256;
            // ---- A tile: row m = f>>3, cols kk0..kk0+3 ----
            {
                int m = f >> 3, kk0 = (f & 7) * 4;
                const float* v = (const float*)&axr[i];
                int r = m & 15, mf = m >> 4;
#pragma unroll
                for (int p = 0; p < 2; p++) {
                    int cix = kk0 + p * 2;              // even
                    __nv_bfloat16 h0, l0, h1, l1;
                    split2(v[p * 2],     h0, l0);
                    split2(v[p * 2 + 1], h1, l1);
                    int k16 = cix >> 4, cc = cix & 15;
                    int ln   = ((r & 7) << 2) | ((cc >> 1) & 3);
                    int slot = ((cc >> 3) << 1) | (r >> 3);
                    int idx  = ((k16 * 8 + mf) * 32 + ln) * 4 + slot;
                    base[OFF_AH + idx] = pack_bf2(h0, h1);
                    base[OFF_AL + idx] = pack_bf2(l0, l1);
                }
            }
            // ---- B tile: row kk = f>>5, cols n0..n0+3 ----
            {
                int kk = f >> 5, n0 = (f & 31) * 4;
                int k16 = kk >> 4, cc = kk & 15;
                int slot = (cc >> 3) & 1, half = cc & 1;
                const float* v = (const float*)&bxr[i];
#pragma unroll
                for (int j = 0; j < 4; j++) {
                    int n = n0 + j;
                    __nv_bfloat16 h, l;
                    split2(v[j], h, l);
                    int nf = n >> 3;
                    int ln = ((n & 7) << 2) | ((cc >> 1) & 3);
                    int idx = ((k16 * 16 + nf) * 32 + ln) * 2 + slot;
                    ((__nv_bfloat16*)(base + OFF_BH))[idx * 2 + half] = h;
                    ((__nv_bfloat16*)(base + OFF_BL))[idx * 2 + half] = l;
                }
            }
        }
    };

    gload(0);
    sstore(0);

    for (int c = 0; c < NCH; c++) {
        if (c + 1 < NCH) gload(c + 1);
        __syncthreads();
        const uint32_t* buf = sm4 + (c & 1) * BUF_W;
#pragma unroll
        for (int k16 = 0; k16 < 2; k16++) {
            uint32_t ah[4][4], al[4][4], bh[4][2], bl[4][2];
#pragma unroll
            for (int mfi = 0; mfi < 4; mfi++)
                *(uint4*)ah[mfi] = *(const uint4*)
                    &buf[OFF_AH + (((k16 * 8) + wm * 4 + mfi) * 32 + lane) * 4];
#pragma unroll
            for (int nfi = 0; nfi < 4; nfi++)
                *(uint2*)bh[nfi] = *(const uint2*)
                    &buf[OFF_BH + (((k16 * 16) + wn * 4 + nfi) * 32 + lane) * 2];
            // pass 1: hi * hi
#pragma unroll
            for (int mfi = 0; mfi < 4; mfi++)
#pragma unroll
                for (int nfi = 0; nfi < 4; nfi++)
                    mma16816(acc[mfi][nfi], ah[mfi], bh[nfi]);
            // pass 2: hi * lo
#pragma unroll
            for (int nfi = 0; nfi < 4; nfi++)
                *(uint2*)bl[nfi] = *(const uint2*)
                    &buf[OFF_BL + (((k16 * 16) + wn * 4 + nfi) * 32 + lane) * 2];
#pragma unroll
            for (int mfi = 0; mfi < 4; mfi++)
#pragma unroll
                for (int nfi = 0; nfi < 4; nfi++)
                    mma16816(acc[mfi][nfi], ah[mfi], bl[nfi]);
            // pass 3: lo * hi
#pragma unroll
            for (int mfi = 0; mfi < 4; mfi++)
                *(uint4*)al[mfi] = *(const uint4*)
                    &buf[OFF_AL + (((k16 * 8) + wm * 4 + mfi) * 32 + lane) * 4];
#pragma unroll
            for (int mfi = 0; mfi < 4; mfi++)
#pragma unroll
                for (int nfi = 0; nfi < 4; nfi++)
                    mma16816(acc[mfi][nfi], al[mfi], bh[nfi]);
        }
        if (c + 1 < NCH) sstore((c + 1) & 1);
    }

    // epilogue
#pragma unroll
    for (int mfi = 0; mfi < 4; mfi++)
#pragma unroll
        for (int nfi = 0; nfi < 4; nfi++) {
            int row = bm * BM + wm * 64 + mfi * 16 + (lane >> 2);
            int col = bn * BN + wn * 32 + nfi * 8 + (lane & 3) * 2;
            float2 v0 = make_float2(acc[mfi][nfi][0], acc[mfi][nfi][1]);
            float2 v1 = make_float2(acc[mfi][nfi][2], acc[mfi][nfi][3]);
            *(float2*)&C[(size_t)row * DM + col]       = v0;
            *(float2*)&C[(size_t)(row + 8) * DM + col] = v1;
        }
}

__global__ __launch_bounds__(256, 1)
void qkv_mma_kernel(const float* __restrict__ x,
                    const float* __restrict__ Wq,
                    const float* __restrict__ Wk,
                    const float* __restrict__ Wv)
{
    const float* W; float* C;
    if (blockIdx.z == 0)      { W = Wq; C = g_Q; }
    else if (blockIdx.z == 1) { W = Wk; C = g_K; }
    else                      { W = Wv; C = g_V; }
    gemm_body(x, W, C);
}

__global__ __launch_bounds__(256, 1)
void out_mma_kernel(const float* __restrict__ Wo, float* __restrict__ out)
{
    gemm_body(g_A, Wo, out);
}

// ---- Attention (fp32 flash-style, unchanged from R1) -----------------------
__global__ __launch_bounds__(128)
void attn_kernel(const unsigned char* __restrict__ pad)
{
    __shared__ float Ks[64][64];
    __shared__ float Vs[64][64];
    __shared__ unsigned char pm[64];

    const int tid = threadIdx.x;
    const int b   = blockIdx.y >> 4;
    const int h   = blockIdx.y & 15;
    const int i   = blockIdx.x * 128 + tid;

    const float* Qrow = g_Q + (size_t)(b * SEQ + i) * DM + h * HD;
    float q[HD];
#pragma unroll
    for (int d4 = 0; d4 < 16; d4++) {
        float4 v = *(const float4*)(Qrow + d4 * 4);
        q[d4*4+0] = v.x * ATT_SCALE; q[d4*4+1] = v.y * ATT_SCALE;
        q[d4*4+2] = v.z * ATT_SCALE; q[d4*4+3] = v.w * ATT_SCALE;
    }

    float o[HD];
#pragma unroll
    for (int d = 0; d < HD; d++) o[d] = 0.f;
    float m = -CUDART_INF_F, l = 0.f;

    const int ntiles = blockIdx.x * 2 + 2;
    for (int kt = 0; kt < ntiles; kt++) {
        const int k0 = kt * 64;
        const float* Kb = g_K + (size_t)(b * SEQ + k0) * DM + h * HD;
        const float* Vb = g_V + (size_t)(b * SEQ + k0) * DM + h * HD;
#pragma unroll
        for (int r = 0; r < 8; r++) {
            int f = r * 128 + tid, row = f >> 4, c4 = (f & 15) * 4;
            *(float4*)&Ks[row][c4] = *(const float4*)(Kb + (size_t)row * DM + c4);
            *(float4*)&Vs[row][c4] = *(const float4*)(Vb + (size_t)row * DM + c4);
        }
        if (tid < 64) pm[tid] = pad[b * SEQ + k0 + tid];
        __syncthreads();

        int jmax = i - k0 + 1;
        if (jmax > 64) jmax = 64;
        for (int j = 0; j < jmax; j++) {
            if (pm[j]) continue;
            float s = 0.f;
#pragma unroll
            for (int d4 = 0; d4 < 16; d4++) {
                float4 kv = *(const float4*)&Ks[j][d4 * 4];
                s += q[d4*4+0]*kv.x; s += q[d4*4+1]*kv.y;
                s += q[d4*4+2]*kv.z; s += q[d4*4+3]*kv.w;
            }
            if (s > m) {
                float alpha = __expf(m - s);
                m = s; l *= alpha;
#pragma unroll
                for (int d = 0; d < HD; d++) o[d] *= alpha;
            }
            float p = __expf(s - m);
            l += p;
#pragma unroll
            for (int d4 = 0; d4 < 16; d4++) {
                float4 vv = *(const float4*)&Vs[j][d4 * 4];
                o[d4*4+0] = fmaf(p, vv.x, o[d4*4+0]);
                o[d4*4+1] = fmaf(p, vv.y, o[d4*4+1]);
                o[d4*4+2] = fmaf(p, vv.z, o[d4*4+2]);
                o[d4*4+3] = fmaf(p, vv.w, o[d4*4+3]);
            }
        }
        __syncthreads();
    }

    float inv = (l > 0.f) ? (1.f / l) : 0.f;
    float* Orow = g_A + (size_t)(b * SEQ + i) * DM + h * HD;
#pragma unroll
    for (int d4 = 0; d4 < 16; d4++) {
        float4 v;
        v.x = o[d4*4+0]*inv; v.y = o[d4*4+1]*inv;
        v.z = o[d4*4+2]*inv; v.w = o[d4*4+3]*inv;
        *(float4*)(Orow + d4 * 4) = v;
    }
}

// ---- Launch -----------------------------------------------------------------
extern "C" void kernel_launch(void* const* d_in, const int* in_sizes, int n_in,
                              void* d_out, int out_size)
{
    (void)in_sizes; (void)n_in; (void)out_size;
    const float*         x   = (const float*)d_in[0];
    const unsigned char* pad = (const unsigned char*)d_in[1];
    const float*         Wq  = (const float*)d_in[2];
    const float*         Wk  = (const float*)d_in[3];
    const float*         Wv  = (const float*)d_in[4];
    const float*         Wo  = (const float*)d_in[5];
    float*               out = (float*)d_out;

    cudaFuncSetAttribute(qkv_mma_kernel, cudaFuncAttributeMaxDynamicSharedMemorySize, GEMM_SMEM_BYTES);
    cudaFuncSetAttribute(out_mma_kernel, cudaFuncAttributeMaxDynamicSharedMemorySize, GEMM_SMEM_BYTES);

    qkv_mma_kernel<<<dim3(DM / BN, MROWS / BM, 3), 256, GEMM_SMEM_BYTES>>>(x, Wq, Wk, Wv);

    attn_kernel<<<dim3(SEQ / 128, BATCH * NH), 128>>>(pad);

    out_mma_kernel<<<dim3(DM / BN, MROWS / BM), 256, GEMM_SMEM_BYTES>>>(Wo, out);
}

// round 4
// speedup vs baseline: 1.8250x; 1.8250x over previous
#include <cuda_runtime.h>
#include <cuda_bf16.h>
#include <math_constants.h>
#include <cstdint>

// ---------------------------------------------------------------------------
// MHA Round 4: bf16 split-GEMM via ldmatrix + cp.async 3-stage pipeline.
// Conversion (fp32 -> hi/lo bf16, W transpose) hoisted to tiny kernels.
// Attention: fp32 flash-style with 4-way dot ILP.
// ---------------------------------------------------------------------------

#define BATCH 4
#define SEQ   2048
#define DM    1024
#define NH    16
#define HD    64
#define MROWS (BATCH * SEQ)   // 8192
#define ATT_SCALE 0.125f

#define BM 128
#define BN 128
#define BK 32
#define NCH (DM / BK)          // 32
#define STAGES 3
#define PITCH 40               // bf16 elems per smem row (80B, conflict-free)
#define TILE_B (128 * PITCH * 2)          // 10240 bytes per tile
#define STAGE_B (4 * TILE_B)              // 40960
#define GEMM_SMEM (STAGES * STAGE_B)      // 122880

// ---- scratch (device globals: allocation-free) -----------------------------
__device__ float g_Q[MROWS * DM];
__device__ float g_K[MROWS * DM];
__device__ float g_V[MROWS * DM];
__device__ float g_A[MROWS * DM];
__device__ __align__(256) __nv_bfloat16 g_xh[MROWS * DM];
__device__ __align__(256) __nv_bfloat16 g_xl[MROWS * DM];
__device__ __align__(256) __nv_bfloat16 g_ah[MROWS * DM];
__device__ __align__(256) __nv_bfloat16 g_al[MROWS * DM];
__device__ __align__(256) __nv_bfloat16 g_wth[4][DM * DM];  // W^T hi [n][k]
__device__ __align__(256) __nv_bfloat16 g_wtl[4][DM * DM];  // W^T lo [n][k]

// ---- helpers ----------------------------------------------------------------
__device__ __forceinline__ uint32_t smem_to_u32(const void* p) {
    uint32_t a;
    asm("{ .reg .u64 t; cvta.to.shared.u64 t, %1; cvt.u32.u64 %0, t; }"
        : "=r"(a) : "l"(p));
    return a;
}
__device__ __forceinline__ void mma16816(float* d, const uint32_t* a, const uint32_t* b) {
    asm volatile(
        "mma.sync.aligned.m16n8k16.row.col.f32.bf16.bf16.f32 "
        "{%0,%1,%2,%3}, {%4,%5,%6,%7}, {%8,%9}, {%0,%1,%2,%3};\n"
        : "+f"(d[0]), "+f"(d[1]), "+f"(d[2]), "+f"(d[3])
        : "r"(a[0]), "r"(a[1]), "r"(a[2]), "r"(a[3]), "r"(b[0]), "r"(b[1]));
}
__device__ __forceinline__ void ldsm_x4(uint32_t* r, uint32_t addr) {
    asm volatile("ldmatrix.sync.aligned.m8n8.x4.shared.b16 {%0,%1,%2,%3}, [%4];"
        : "=r"(r[0]), "=r"(r[1]), "=r"(r[2]), "=r"(r[3]) : "r"(addr));
}
__device__ __forceinline__ void cpasync16(uint32_t dst, const void* src) {
    asm volatile("cp.async.cg.shared.global [%0], [%1], 16;" :: "r"(dst), "l"(src));
}
__device__ __forceinline__ void split2(float v, __nv_bfloat16& h, __nv_bfloat16& l) {
    h = __float2bfloat16(v);
    l = __float2bfloat16(v - __bfloat162float(h));
}
__device__ __forceinline__ uint32_t pack_bf2(__nv_bfloat16 a, __nv_bfloat16 b) {
    __nv_bfloat162 t = __halves2bfloat162(a, b);
    return *(uint32_t*)&t;
}

// ---- GEMM: C[8192,1024] = A @ W (A,W pre-split bf16; W pre-transposed) -----
__device__ __forceinline__ void gemm_body(
    const __nv_bfloat16* __restrict__ Ah, const __nv_bfloat16* __restrict__ Al,
    const __nv_bfloat16* __restrict__ Bh, const __nv_bfloat16* __restrict__ Bl,
    float* __restrict__ C)
{
    extern __shared__ char smem[];
    const uint32_t sb = smem_to_u32(smem);
    const int tid  = threadIdx.x;
    const int lane = tid & 31;
    const int wid  = tid >> 5;
    const int wm   = wid >> 2;           // 0..1
    const int wn   = wid & 3;            // 0..3
    const int bm = blockIdx.y, bn = blockIdx.x;

    const __nv_bfloat16* gsrc[4] = {
        Ah + (size_t)bm * BM * DM,
        Al + (size_t)bm * BM * DM,
        Bh + (size_t)bn * BN * DM,
        Bl + (size_t)bn * BN * DM
    };

    float acc[4][4][4];
#pragma unroll
    for (int i = 0; i < 4; i++)
#pragma unroll
        for (int j = 0; j < 4; j++)
#pragma unroll
            for (int r = 0; r < 4; r++) acc[i][j][r] = 0.f;

    auto issue = [&](int c) {
        if (c < NCH) {
            const uint32_t sbase = sb + (c % STAGES) * STAGE_B;
            const size_t koff = (size_t)c * BK;
#pragma unroll
            for (int i = 0; i < 8; i++) {
                int q   = tid + i * 256;        // 0..2047
                int t   = q >> 9;               // tile 0..3
                int r   = (q >> 2) & 127;       // row
                int c16 = q & 3;                // 16B chunk in row
                const __nv_bfloat16* src = gsrc[t] + (size_t)r * DM + koff + c16 * 8;
                uint32_t dst = sbase + t * TILE_B + (r * PITCH + c16 * 8) * 2;
                cpasync16(dst, src);
            }
        }
        asm volatile("cp.async.commit_group;");
    };

    // prologue: STAGES-1 stages in flight
    issue(0);
    issue(1);

    // lane -> ldmatrix source row/col (within warp tile)
    const int a_r = (lane & 7) + ((lane >> 3) & 1) * 8;   // A: +8 rows for lanes 8-15,24-31
    const int a_c = (lane >> 4) * 8;                      // A: +8 cols for lanes 16-31
    const int b_r = (lane & 7) + ((lane >> 4) & 1) * 8;   // B: +8 rows for lanes 16-31
    const int b_c = ((lane >> 3) & 1) * 8;                // B: +8 cols for lanes 8-15,24-31

    for (int c = 0; c < NCH; c++) {
        issue(c + STAGES - 1);
        asm volatile("cp.async.wait_group %0;" :: "n"(STAGES - 1));
        __syncthreads();

        const uint32_t st = sb + (c % STAGES) * STAGE_B;
        const uint32_t sAh = st, sAl = st + TILE_B, sBh = st + 2 * TILE_B, sBl = st + 3 * TILE_B;

#pragma unroll
        for (int k16 = 0; k16 < 2; k16++) {
            const int kc = k16 * 16;
            uint32_t ah[4][4], al[4][4], bh[2][4], bl[2][4];
            // A hi fragments (4x m16)
#pragma unroll
            for (int mfi = 0; mfi < 4; mfi++)
                ldsm_x4(ah[mfi], sAh + ((wm * 64 + mfi * 16 + a_r) * PITCH + kc + a_c) * 2);
            // B hi fragments (2x x4 = 4 n8 frags)
#pragma unroll
            for (int nfp = 0; nfp < 2; nfp++)
                ldsm_x4(bh[nfp], sBh + ((wn * 32 + nfp * 16 + b_r) * PITCH + kc + b_c) * 2);
            // pass 1: hi*hi
#pragma unroll
            for (int mfi = 0; mfi < 4; mfi++)
#pragma unroll
                for (int nf = 0; nf < 4; nf++)
                    mma16816(acc[mfi][nf], ah[mfi], &bh[nf >> 1][(nf & 1) * 2]);
            // pass 2: hi*lo
#pragma unroll
            for (int nfp = 0; nfp < 2; nfp++)
                ldsm_x4(bl[nfp], sBl + ((wn * 32 + nfp * 16 + b_r) * PITCH + kc + b_c) * 2);
#pragma unroll
            for (int mfi = 0; mfi < 4; mfi++)
#pragma unroll
                for (int nf = 0; nf < 4; nf++)
                    mma16816(acc[mfi][nf], ah[mfi], &bl[nf >> 1][(nf & 1) * 2]);
            // pass 3: lo*hi
#pragma unroll
            for (int mfi = 0; mfi < 4; mfi++)
                ldsm_x4(al[mfi], sAl + ((wm * 64 + mfi * 16 + a_r) * PITCH + kc + a_c) * 2);
#pragma unroll
            for (int mfi = 0; mfi < 4; mfi++)
#pragma unroll
                for (int nf = 0; nf < 4; nf++)
                    mma16816(acc[mfi][nf], al[mfi], &bh[nf >> 1][(nf & 1) * 2]);
        }
        __syncthreads();   // all warps done with this stage before its buffer is refilled
    }

    // epilogue
#pragma unroll
    for (int mfi = 0; mfi < 4; mfi++)
#pragma unroll
        for (int nf = 0; nf < 4; nf++) {
            int row = bm * BM + wm * 64 + mfi * 16 + (lane >> 2);
            int col = bn * BN + wn * 32 + nf * 8 + (lane & 3) * 2;
            *(float2*)&C[(size_t)row * DM + col]       = make_float2(acc[mfi][nf][0], acc[mfi][nf][1]);
            *(float2*)&C[(size_t)(row + 8) * DM + col] = make_float2(acc[mfi][nf][2], acc[mfi][nf][3]);
        }
}

__global__ __launch_bounds__(256, 1)
void qkv_mma_kernel()
{
    const int z = blockIdx.z;
    float* C = (z == 0) ? g_Q : (z == 1) ? g_K : g_V;
    gemm_body(g_xh, g_xl, g_wth[z], g_wtl[z], C);
}
__global__ __launch_bounds__(256, 1)
void out_mma_kernel(float* __restrict__ out)
{
    gemm_body(g_ah, g_al, g_wth[3], g_wtl[3], out);
}

// ---- conversion kernels ------------------------------------------------------
__global__ __launch_bounds__(256) void conv_x_kernel(const float* __restrict__ s,
                                                     __nv_bfloat16* __restrict__ dh,
                                                     __nv_bfloat16* __restrict__ dl) {
    int i = blockIdx.x * 256 + threadIdx.x;     // MROWS*DM/4 threads
    float4 v = ((const float4*)s)[i];
    __nv_bfloat16 h0,h1,h2,h3,l0,l1,l2,l3;
    split2(v.x,h0,l0); split2(v.y,h1,l1); split2(v.z,h2,l2); split2(v.w,h3,l3);
    ((uint32_t*)dh)[i*2+0] = pack_bf2(h0,h1);
    ((uint32_t*)dh)[i*2+1] = pack_bf2(h2,h3);
    ((uint32_t*)dl)[i*2+0] = pack_bf2(l0,l1);
    ((uint32_t*)dl)[i*2+1] = pack_bf2(l2,l3);
}
// W [k][n] fp32 -> W^T hi/lo [n][k] bf16 (32x32 smem transpose)
__global__ __launch_bounds__(256) void conv_wt_kernel(const float* __restrict__ W0,
                                                      const float* __restrict__ W1,
                                                      const float* __restrict__ W2,
                                                      const float* __restrict__ W3) {
    __shared__ float tile[32][33];
    const int z = blockIdx.z;
    const float* W = (z == 0) ? W0 : (z == 1) ? W1 : (z == 2) ? W2 : W3;
    const int n0 = blockIdx.x * 32, k0 = blockIdx.y * 32;
    const int tx = threadIdx.x, ty = threadIdx.y;    // 32 x 8
#pragma unroll
    for (int i = ty; i < 32; i += 8)
        tile[i][tx] = W[(size_t)(k0 + i) * DM + n0 + tx];
    __syncthreads();
#pragma unroll
    for (int i = ty; i < 32; i += 8) {
        float v = tile[tx][i];                       // = W[k0+tx][n0+i]
        __nv_bfloat16 h, l; split2(v, h, l);
        g_wth[z][(size_t)(n0 + i) * DM + k0 + tx] = h;
        g_wtl[z][(size_t)(n0 + i) * DM + k0 + tx] = l;
    }
}

// ---- Attention (fp32 flash-style, 4-way dot ILP) -----------------------------
__global__ __launch_bounds__(128)
void attn_kernel(const unsigned char* __restrict__ pad)
{
    __shared__ float Ks[64][64];
    __shared__ float Vs[64][64];
    __shared__ unsigned char pm[64];

    const int tid = threadIdx.x;
    const int b   = blockIdx.y >> 4;
    const int h   = blockIdx.y & 15;
    const int i   = blockIdx.x * 128 + tid;

    const float* Qrow = g_Q + (size_t)(b * SEQ + i) * DM + h * HD;
    float q[HD];
#pragma unroll
    for (int d4 = 0; d4 < 16; d4++) {
        float4 v = *(const float4*)(Qrow + d4 * 4);
        q[d4*4+0] = v.x * ATT_SCALE; q[d4*4+1] = v.y * ATT_SCALE;
        q[d4*4+2] = v.z * ATT_SCALE; q[d4*4+3] = v.w * ATT_SCALE;
    }

    float o[HD];
#pragma unroll
    for (int d = 0; d < HD; d++) o[d] = 0.f;
    float m = -CUDART_INF_F, l = 0.f;

    const int ntiles = blockIdx.x * 2 + 2;
    for (int kt = 0; kt < ntiles; kt++) {
        const int k0 = kt * 64;
        const float* Kb = g_K + (size_t)(b * SEQ + k0) * DM + h * HD;
        const float* Vb = g_V + (size_t)(b * SEQ + k0) * DM + h * HD;
#pragma unroll
        for (int r = 0; r < 8; r++) {
            int f = r * 128 + tid, row = f >> 4, c4 = (f & 15) * 4;
            *(float4*)&Ks[row][c4] = *(const float4*)(Kb + (size_t)row * DM + c4);
            *(float4*)&Vs[row][c4] = *(const float4*)(Vb + (size_t)row * DM + c4);
        }
        if (tid < 64) pm[tid] = pad[b * SEQ + k0 + tid];
        __syncthreads();

        int jmax = i - k0 + 1;
        if (jmax > 64) jmax = 64;
        for (int j = 0; j < jmax; j++) {
            if (pm[j]) continue;
            float s0 = 0.f, s1 = 0.f, s2 = 0.f, s3 = 0.f;
#pragma unroll
            for (int d4 = 0; d4 < 16; d4 += 4) {
                float4 k0v = *(const float4*)&Ks[j][d4 * 4];
                float4 k1v = *(const float4*)&Ks[j][d4 * 4 + 4];
                float4 k2v = *(const float4*)&Ks[j][d4 * 4 + 8];
                float4 k3v = *(const float4*)&Ks[j][d4 * 4 + 12];
                s0 = fmaf(q[d4*4+0], k0v.x, s0); s0 = fmaf(q[d4*4+1], k0v.y, s0);
                s0 = fmaf(q[d4*4+2], k0v.z, s0); s0 = fmaf(q[d4*4+3], k0v.w, s0);
                s1 = fmaf(q[d4*4+4], k1v.x, s1); s1 = fmaf(q[d4*4+5], k1v.y, s1);
                s1 = fmaf(q[d4*4+6], k1v.z, s1); s1 = fmaf(q[d4*4+7], k1v.w, s1);
                s2 = fmaf(q[d4*4+8], k2v.x, s2); s2 = fmaf(q[d4*4+9], k2v.y, s2);
                s2 = fmaf(q[d4*4+10], k2v.z, s2); s2 = fmaf(q[d4*4+11], k2v.w, s2);
                s3 = fmaf(q[d4*4+12], k3v.x, s3); s3 = fmaf(q[d4*4+13], k3v.y, s3);
                s3 = fmaf(q[d4*4+14], k3v.z, s3); s3 = fmaf(q[d4*4+15], k3v.w, s3);
            }
            float s = (s0 + s1) + (s2 + s3);
            if (s > m) {
                float alpha = __expf(m - s);
                m = s; l *= alpha;
#pragma unroll
                for (int d = 0; d < HD; d++) o[d] *= alpha;
            }
            float p = __expf(s - m);
            l += p;
#pragma unroll
            for (int d4 = 0; d4 < 16; d4++) {
                float4 vv = *(const float4*)&Vs[j][d4 * 4];
                o[d4*4+0] = fmaf(p, vv.x, o[d4*4+0]);
                o[d4*4+1] = fmaf(p, vv.y, o[d4*4+1]);
                o[d4*4+2] = fmaf(p, vv.z, o[d4*4+2]);
                o[d4*4+3] = fmaf(p, vv.w, o[d4*4+3]);
            }
        }
        __syncthreads();
    }

    float inv = (l > 0.f) ? (1.f / l) : 0.f;
    float* Orow = g_A + (size_t)(b * SEQ + i) * DM + h * HD;
#pragma unroll
    for (int d4 = 0; d4 < 16; d4++) {
        float4 v;
        v.x = o[d4*4+0]*inv; v.y = o[d4*4+1]*inv;
        v.z = o[d4*4+2]*inv; v.w = o[d4*4+3]*inv;
        *(float4*)(Orow + d4 * 4) = v;
    }
}

// ---- Launch -------------------------------------------------------------------
extern "C" void kernel_launch(void* const* d_in, const int* in_sizes, int n_in,
                              void* d_out, int out_size)
{
    (void)in_sizes; (void)n_in; (void)out_size;
    const float*         x   = (const float*)d_in[0];
    const unsigned char* pad = (const unsigned char*)d_in[1];
    const float*         Wq  = (const float*)d_in[2];
    const float*         Wk  = (const float*)d_in[3];
    const float*         Wv  = (const float*)d_in[4];
    const float*         Wo  = (const float*)d_in[5];
    float*               out = (float*)d_out;

    cudaFuncSetAttribute(qkv_mma_kernel, cudaFuncAttributeMaxDynamicSharedMemorySize, GEMM_SMEM);
    cudaFuncSetAttribute(out_mma_kernel, cudaFuncAttributeMaxDynamicSharedMemorySize, GEMM_SMEM);

    // conversions
    __nv_bfloat16 *xh, *xl, *ah, *al;
    cudaGetSymbolAddress((void**)&xh, g_xh);
    cudaGetSymbolAddress((void**)&xl, g_xl);
    cudaGetSymbolAddress((void**)&ah, g_ah);
    cudaGetSymbolAddress((void**)&al, g_al);

    conv_x_kernel<<<MROWS * DM / 4 / 256, 256>>>(x, xh, xl);
    conv_wt_kernel<<<dim3(DM / 32, DM / 32, 4), dim3(32, 8)>>>(Wq, Wk, Wv, Wo);

    qkv_mma_kernel<<<dim3(DM / BN, MROWS / BM, 3), 256, GEMM_SMEM>>>();

    attn_kernel<<<dim3(SEQ / 128, BATCH * NH), 128>>>(pad);

    float* gA;
    cudaGetSymbolAddress((void**)&gA, g_A);
    conv_x_kernel<<<MROWS * DM / 4 / 256, 256>>>(gA, ah, al);
    out_mma_kernel<<<dim3(DM / BN, MROWS / BM), 256, GEMM_SMEM>>>(out);
}

// round 6
// speedup vs baseline: 3.9155x; 2.1455x over previous
#include <cuda_runtime.h>
#include <cuda_bf16.h>
#include <math_constants.h>
#include <cstdint>

// ---------------------------------------------------------------------------
// MHA Round 6: R5 design with the attention smem pitch bug fixed (APITCH=72).
//  conv_x / conv_wt : fp32 -> split bf16 (+ W transpose)
//  qkv_mma          : x @ Wq/Wk/Wv -> split-bf16 Q(scaled)/K/V directly
//  attn             : warp-tile flash attention, QK & PV both 3-pass split
//  out_mma          : A(split, from attn epilogue) @ Wo -> fp32 out
// ---------------------------------------------------------------------------

#define BATCH 4
#define SEQ   2048
#define DM    1024
#define NH    16
#define HD    64
#define MROWS (BATCH * SEQ)
#define ATT_SCALE 0.125f

#define BM 128
#define BN 128
#define BK 32
#define NCH (DM / BK)
#define STAGES 3
#define PITCH 40                       // GEMM: 32 data + 8 pad bf16 per row
#define TILE_B (128 * PITCH * 2)       // 10240
#define STAGE_B (4 * TILE_B)
#define GEMM_SMEM (STAGES * STAGE_B)   // 122880

// attention smem: tiles are 64 dims wide -> own pitch
#define APITCH 72                      // 64 data + 8 pad (row stride 144B)
#define AQ_B   (128 * APITCH * 2)      // 18432 per Q operand (hi or lo)
#define AK_B   (64 * APITCH * 2)       // 9216 per K/V operand tile
#define ASTG_B (4 * AK_B)              // 36864 per stage (Kh,Kl,Vh,Vl)
#define AOFF_Q  0
#define AOFF_ST (2 * AQ_B)             // 36864
#define AOFF_PM (AOFF_ST + 2 * ASTG_B) // 110592
#define ATTN_SMEM (AOFF_PM + 512)      // 111104

// ---- scratch (device globals) -----------------------------------------------
__device__ __align__(256) __nv_bfloat16 g_xh[MROWS * DM];
__device__ __align__(256) __nv_bfloat16 g_xl[MROWS * DM];
__device__ __align__(256) __nv_bfloat16 g_qh[MROWS * DM];
__device__ __align__(256) __nv_bfloat16 g_ql[MROWS * DM];
__device__ __align__(256) __nv_bfloat16 g_kh[MROWS * DM];
__device__ __align__(256) __nv_bfloat16 g_kl[MROWS * DM];
__device__ __align__(256) __nv_bfloat16 g_vh[MROWS * DM];
__device__ __align__(256) __nv_bfloat16 g_vl[MROWS * DM];
__device__ __align__(256) __nv_bfloat16 g_ah[MROWS * DM];
__device__ __align__(256) __nv_bfloat16 g_al[MROWS * DM];
__device__ __align__(256) __nv_bfloat16 g_wth[4][DM * DM];
__device__ __align__(256) __nv_bfloat16 g_wtl[4][DM * DM];

// ---- helpers ------------------------------------------------------------------
__device__ __forceinline__ uint32_t smem_to_u32(const void* p) {
    uint32_t a;
    asm("{ .reg .u64 t; cvta.to.shared.u64 t, %1; cvt.u32.u64 %0, t; }"
        : "=r"(a) : "l"(p));
    return a;
}
__device__ __forceinline__ void mma16816(float* d, const uint32_t* a, const uint32_t* b) {
    asm volatile(
        "mma.sync.aligned.m16n8k16.row.col.f32.bf16.bf16.f32 "
        "{%0,%1,%2,%3}, {%4,%5,%6,%7}, {%8,%9}, {%0,%1,%2,%3};\n"
        : "+f"(d[0]), "+f"(d[1]), "+f"(d[2]), "+f"(d[3])
        : "r"(a[0]), "r"(a[1]), "r"(a[2]), "r"(a[3]), "r"(b[0]), "r"(b[1]));
}
__device__ __forceinline__ void ldsm_x4(uint32_t* r, uint32_t addr) {
    asm volatile("ldmatrix.sync.aligned.m8n8.x4.shared.b16 {%0,%1,%2,%3}, [%4];"
        : "=r"(r[0]), "=r"(r[1]), "=r"(r[2]), "=r"(r[3]) : "r"(addr));
}
__device__ __forceinline__ void ldsm_x4_t(uint32_t* r, uint32_t addr) {
    asm volatile("ldmatrix.sync.aligned.m8n8.x4.trans.shared.b16 {%0,%1,%2,%3}, [%4];"
        : "=r"(r[0]), "=r"(r[1]), "=r"(r[2]), "=r"(r[3]) : "r"(addr));
}
__device__ __forceinline__ void cpasync16(uint32_t dst, const void* src) {
    asm volatile("cp.async.cg.shared.global [%0], [%1], 16;" :: "r"(dst), "l"(src));
}
__device__ __forceinline__ void split2(float v, __nv_bfloat16& h, __nv_bfloat16& l) {
    h = __float2bfloat16(v);
    l = __float2bfloat16(v - __bfloat162float(h));
}
__device__ __forceinline__ uint32_t pack_bf2(__nv_bfloat16 a, __nv_bfloat16 b) {
    __nv_bfloat162 t = __halves2bfloat162(a, b);
    return *(uint32_t*)&t;
}
__device__ __forceinline__ uint32_t split_pack_h(float v0, float v1, float& r0, float& r1) {
    __nv_bfloat16 h0 = __float2bfloat16(v0), h1 = __float2bfloat16(v1);
    r0 = v0 - __bfloat162float(h0);
    r1 = v1 - __bfloat162float(h1);
    return pack_bf2(h0, h1);
}

// ---- GEMM body (MODE 0: fp32 C out; MODE 1: split bf16 out, scaled) ----------
template<int MODE>
__device__ __forceinline__ void gemm_body(
    const __nv_bfloat16* __restrict__ Ah, const __nv_bfloat16* __restrict__ Al,
    const __nv_bfloat16* __restrict__ Bh, const __nv_bfloat16* __restrict__ Bl,
    float* __restrict__ C, __nv_bfloat16* __restrict__ Ch,
    __nv_bfloat16* __restrict__ Cl, float scale)
{
    extern __shared__ char smem[];
    const uint32_t sb = smem_to_u32(smem);
    const int tid  = threadIdx.x;
    const int lane = tid & 31;
    const int wid  = tid >> 5;
    const int wm   = wid >> 2;
    const int wn   = wid & 3;
    const int bm = blockIdx.y, bn = blockIdx.x;

    const __nv_bfloat16* gsrc[4] = {
        Ah + (size_t)bm * BM * DM, Al + (size_t)bm * BM * DM,
        Bh + (size_t)bn * BN * DM, Bl + (size_t)bn * BN * DM
    };

    float acc[4][4][4];
#pragma unroll
    for (int i = 0; i < 4; i++)
#pragma unroll
        for (int j = 0; j < 4; j++)
#pragma unroll
            for (int r = 0; r < 4; r++) acc[i][j][r] = 0.f;

    auto issue = [&](int c) {
        if (c < NCH) {
            const uint32_t sbase = sb + (c % STAGES) * STAGE_B;
            const size_t koff = (size_t)c * BK;
#pragma unroll
            for (int i = 0; i < 8; i++) {
                int q = tid + i * 256;
                int t = q >> 9, r = (q >> 2) & 127, c16 = q & 3;
                cpasync16(sbase + t * TILE_B + (r * PITCH + c16 * 8) * 2,
                          gsrc[t] + (size_t)r * DM + koff + c16 * 8);
            }
        }
        asm volatile("cp.async.commit_group;");
    };

    issue(0); issue(1);

    const int a_r = (lane & 7) + ((lane >> 3) & 1) * 8;
    const int a_c = (lane >> 4) * 8;
    const int b_r = (lane & 7) + ((lane >> 4) & 1) * 8;
    const int b_c = ((lane >> 3) & 1) * 8;

    for (int c = 0; c < NCH; c++) {
        issue(c + STAGES - 1);
        asm volatile("cp.async.wait_group %0;" :: "n"(STAGES - 1));
        __syncthreads();

        const uint32_t st = sb + (c % STAGES) * STAGE_B;
        const uint32_t sAh = st, sAl = st + TILE_B, sBh = st + 2 * TILE_B, sBl = st + 3 * TILE_B;

#pragma unroll
        for (int k16 = 0; k16 < 2; k16++) {
            const int kc = k16 * 16;
            uint32_t ah[4][4], al[4][4], bh[2][4], bl[2][4];
#pragma unroll
            for (int mfi = 0; mfi < 4; mfi++)
                ldsm_x4(ah[mfi], sAh + ((wm * 64 + mfi * 16 + a_r) * PITCH + kc + a_c) * 2);
#pragma unroll
            for (int nfp = 0; nfp < 2; nfp++)
                ldsm_x4(bh[nfp], sBh + ((wn * 32 + nfp * 16 + b_r) * PITCH + kc + b_c) * 2);
#pragma unroll
            for (int mfi = 0; mfi < 4; mfi++)
#pragma unroll
                for (int nf = 0; nf < 4; nf++)
                    mma16816(acc[mfi][nf], ah[mfi], &bh[nf >> 1][(nf & 1) * 2]);
#pragma unroll
            for (int nfp = 0; nfp < 2; nfp++)
                ldsm_x4(bl[nfp], sBl + ((wn * 32 + nfp * 16 + b_r) * PITCH + kc + b_c) * 2);
#pragma unroll
            for (int mfi = 0; mfi < 4; mfi++)
#pragma unroll
                for (int nf = 0; nf < 4; nf++)
                    mma16816(acc[mfi][nf], ah[mfi], &bl[nf >> 1][(nf & 1) * 2]);
#pragma unroll
            for (int mfi = 0; mfi < 4; mfi++)
                ldsm_x4(al[mfi], sAl + ((wm * 64 + mfi * 16 + a_r) * PITCH + kc + a_c) * 2);
#pragma unroll
            for (int mfi = 0; mfi < 4; mfi++)
#pragma unroll
                for (int nf = 0; nf < 4; nf++)
                    mma16816(acc[mfi][nf], al[mfi], &bh[nf >> 1][(nf & 1) * 2]);
        }
        __syncthreads();
    }

#pragma unroll
    for (int mfi = 0; mfi < 4; mfi++)
#pragma unroll
        for (int nf = 0; nf < 4; nf++) {
            int row = bm * BM + wm * 64 + mfi * 16 + (lane >> 2);
            int col = bn * BN + wn * 32 + nf * 8 + (lane & 3) * 2;
            if (MODE == 0) {
                *(float2*)&C[(size_t)row * DM + col]       = make_float2(acc[mfi][nf][0], acc[mfi][nf][1]);
                *(float2*)&C[(size_t)(row + 8) * DM + col] = make_float2(acc[mfi][nf][2], acc[mfi][nf][3]);
            } else {
                float v0 = acc[mfi][nf][0] * scale, v1 = acc[mfi][nf][1] * scale;
                float v2 = acc[mfi][nf][2] * scale, v3 = acc[mfi][nf][3] * scale;
                __nv_bfloat16 h0, l0, h1, l1, h2, l2, h3, l3;
                split2(v0, h0, l0); split2(v1, h1, l1);
                split2(v2, h2, l2); split2(v3, h3, l3);
                *(uint32_t*)&Ch[(size_t)row * DM + col]       = pack_bf2(h0, h1);
                *(uint32_t*)&Ch[(size_t)(row + 8) * DM + col] = pack_bf2(h2, h3);
                *(uint32_t*)&Cl[(size_t)row * DM + col]       = pack_bf2(l0, l1);
                *(uint32_t*)&Cl[(size_t)(row + 8) * DM + col] = pack_bf2(l2, l3);
            }
        }
}

__global__ __launch_bounds__(256, 1)
void qkv_mma_kernel()
{
    const int z = blockIdx.z;
    __nv_bfloat16 *Ch, *Cl; float sc;
    if (z == 0)      { Ch = g_qh; Cl = g_ql; sc = ATT_SCALE; }
    else if (z == 1) { Ch = g_kh; Cl = g_kl; sc = 1.f; }
    else             { Ch = g_vh; Cl = g_vl; sc = 1.f; }
    gemm_body<1>(g_xh, g_xl, g_wth[z], g_wtl[z], nullptr, Ch, Cl, sc);
}
__global__ __launch_bounds__(256, 1)
void out_mma_kernel(float* __restrict__ out)
{
    gemm_body<0>(g_ah, g_al, g_wth[3], g_wtl[3], out, nullptr, nullptr, 1.f);
}

// ---- conversion kernels ---------------------------------------------------------
__global__ __launch_bounds__(256) void conv_x_kernel(const float* __restrict__ s,
                                                     __nv_bfloat16* __restrict__ dh,
                                                     __nv_bfloat16* __restrict__ dl) {
    int i = blockIdx.x * 256 + threadIdx.x;
    float4 v = ((const float4*)s)[i];
    __nv_bfloat16 h0,h1,h2,h3,l0,l1,l2,l3;
    split2(v.x,h0,l0); split2(v.y,h1,l1); split2(v.z,h2,l2); split2(v.w,h3,l3);
    ((uint32_t*)dh)[i*2+0] = pack_bf2(h0,h1);
    ((uint32_t*)dh)[i*2+1] = pack_bf2(h2,h3);
    ((uint32_t*)dl)[i*2+0] = pack_bf2(l0,l1);
    ((uint32_t*)dl)[i*2+1] = pack_bf2(l2,l3);
}
__global__ __launch_bounds__(256) void conv_wt_kernel(const float* __restrict__ W0,
                                                      const float* __restrict__ W1,
                                                      const float* __restrict__ W2,
                                                      const float* __restrict__ W3) {
    __shared__ float tile[32][33];
    const int z = blockIdx.z;
    const float* W = (z == 0) ? W0 : (z == 1) ? W1 : (z == 2) ? W2 : W3;
    const int n0 = blockIdx.x * 32, k0 = blockIdx.y * 32;
    const int tx = threadIdx.x, ty = threadIdx.y;
#pragma unroll
    for (int i = ty; i < 32; i += 8)
        tile[i][tx] = W[(size_t)(k0 + i) * DM + n0 + tx];
    __syncthreads();
#pragma unroll
    for (int i = ty; i < 32; i += 8) {
        float v = tile[tx][i];
        __nv_bfloat16 h, l; split2(v, h, l);
        g_wth[z][(size_t)(n0 + i) * DM + k0 + tx] = h;
        g_wtl[z][(size_t)(n0 + i) * DM + k0 + tx] = l;
    }
}

// ---- Flash attention on tensor cores ---------------------------------------------
__global__ __launch_bounds__(256, 1)
void attn_kernel(const unsigned char* __restrict__ pad)
{
    extern __shared__ char smem[];
    const uint32_t sb = smem_to_u32(smem);
    const int tid = threadIdx.x, lane = tid & 31, wq = tid >> 5;
    const int b = blockIdx.y >> 4, h = blockIdx.y & 15;
    const int qbase = blockIdx.x * 128;
    const int ntiles = blockIdx.x * 2 + 2;

    // ---- Q tile load (bundled into commit group 0 with stage 0) ----
    {
        const __nv_bfloat16* srcq[2] = {
            g_qh + (size_t)(b * SEQ + qbase) * DM + h * HD,
            g_ql + (size_t)(b * SEQ + qbase) * DM + h * HD };
#pragma unroll
        for (int i = 0; i < 8; i++) {
            int q = tid + i * 256;
            int op = q >> 10, row = (q >> 3) & 127, ch = q & 7;
            cpasync16(sb + AOFF_Q + op * AQ_B + (row * APITCH + ch * 8) * 2,
                      srcq[op] + (size_t)row * DM + ch * 8);
        }
    }

    auto issue = [&](int t) {
        if (t < ntiles) {
            const int k0 = t * 64;
            const uint32_t sbase = sb + AOFF_ST + (t & 1) * ASTG_B;
            const __nv_bfloat16* gs[4] = {
                g_kh + (size_t)(b * SEQ + k0) * DM + h * HD,
                g_kl + (size_t)(b * SEQ + k0) * DM + h * HD,
                g_vh + (size_t)(b * SEQ + k0) * DM + h * HD,
                g_vl + (size_t)(b * SEQ + k0) * DM + h * HD };
#pragma unroll
            for (int i = 0; i < 8; i++) {
                int q = tid + i * 256;
                int tt = q >> 9, row = (q >> 3) & 63, ch = q & 7;
                cpasync16(sbase + tt * AK_B + (row * APITCH + ch * 8) * 2,
                          gs[tt] + (size_t)row * DM + ch * 8);
            }
        }
        asm volatile("cp.async.commit_group;");
    };
    auto pmload = [&](int t) {
        if (t < ntiles && tid < 64) {
            float v = pad[b * SEQ + t * 64 + tid] ? -CUDART_INF_F : 0.f;
            *(float*)(smem + AOFF_PM + (t & 1) * 256 + tid * 4) = v;
        }
    };

    pmload(0); issue(0);
    pmload(1); issue(1);

    const int r  = lane >> 2;
    const int c2 = (lane & 3) * 2;
    const int row0 = qbase + wq * 16 + r;
    const int row1 = row0 + 8;
    const int qmax = qbase + wq * 16 + 15;

    const int a_r = (lane & 7) + ((lane >> 3) & 1) * 8;
    const int a_c = (lane >> 4) * 8;
    const int b_r = (lane & 7) + ((lane >> 4) & 1) * 8;   // K non-trans
    const int b_c = ((lane >> 3) & 1) * 8;
    const int v_r = (lane & 7) + ((lane >> 3) & 1) * 8;   // V trans
    const int v_c = (lane >> 4) * 8;

    float m0 = -CUDART_INF_F, m1 = -CUDART_INF_F, l0 = 0.f, l1 = 0.f;
    float o[8][4];
#pragma unroll
    for (int i = 0; i < 8; i++)
#pragma unroll
        for (int j = 0; j < 4; j++) o[i][j] = 0.f;

    uint32_t qfh[4][4], qfl[4][4];

    for (int t = 0; t < ntiles; t++) {
        asm volatile("cp.async.wait_group %0;" :: "n"(1));
        __syncthreads();

        if (t == 0) {
#pragma unroll
            for (int dk = 0; dk < 4; dk++) {
                ldsm_x4(qfh[dk], sb + AOFF_Q +        ((wq * 16 + a_r) * APITCH + dk * 16 + a_c) * 2);
                ldsm_x4(qfl[dk], sb + AOFF_Q + AQ_B + ((wq * 16 + a_r) * APITCH + dk * 16 + a_c) * 2);
            }
        }

        const int k0 = t * 64;
        if (k0 <= qmax) {
            const uint32_t st = sb + AOFF_ST + (t & 1) * ASTG_B;
            // ---- S = Q K^T (3-pass split) ----
            float s[8][4];
#pragma unroll
            for (int f = 0; f < 8; f++)
#pragma unroll
                for (int j = 0; j < 4; j++) s[f][j] = 0.f;

#pragma unroll
            for (int dk = 0; dk < 4; dk++) {
                uint32_t kf[4][4];
#pragma unroll
                for (int g = 0; g < 4; g++)
                    ldsm_x4(kf[g], st + ((g * 16 + b_r) * APITCH + dk * 16 + b_c) * 2);
#pragma unroll
                for (int f = 0; f < 8; f++)
                    mma16816(s[f], qfh[dk], &kf[f >> 1][(f & 1) * 2]);
#pragma unroll
                for (int f = 0; f < 8; f++)
                    mma16816(s[f], qfl[dk], &kf[f >> 1][(f & 1) * 2]);
            }
#pragma unroll
            for (int dk = 0; dk < 4; dk++) {
                uint32_t kf[4][4];
#pragma unroll
                for (int g = 0; g < 4; g++)
                    ldsm_x4(kf[g], st + AK_B + ((g * 16 + b_r) * APITCH + dk * 16 + b_c) * 2);
#pragma unroll
                for (int f = 0; f < 8; f++)
                    mma16816(s[f], qfh[dk], &kf[f >> 1][(f & 1) * 2]);
            }

            // ---- masks ----
            const bool needc = (k0 + 63 > row0);
#pragma unroll
            for (int f = 0; f < 8; f++) {
                float2 pmv = *(float2*)(smem + AOFF_PM + (t & 1) * 256 + (f * 8 + c2) * 4);
                s[f][0] += pmv.x; s[f][1] += pmv.y;
                s[f][2] += pmv.x; s[f][3] += pmv.y;
                if (needc) {
                    int k = k0 + f * 8 + c2;
                    if (k     > row0) s[f][0] = -CUDART_INF_F;
                    if (k + 1 > row0) s[f][1] = -CUDART_INF_F;
                    if (k     > row1) s[f][2] = -CUDART_INF_F;
                    if (k + 1 > row1) s[f][3] = -CUDART_INF_F;
                }
            }

            // ---- online softmax ----
            float mx0 = -CUDART_INF_F, mx1 = -CUDART_INF_F;
#pragma unroll
            for (int f = 0; f < 8; f++) {
                mx0 = fmaxf(mx0, fmaxf(s[f][0], s[f][1]));
                mx1 = fmaxf(mx1, fmaxf(s[f][2], s[f][3]));
            }
            mx0 = fmaxf(mx0, __shfl_xor_sync(0xffffffff, mx0, 1));
            mx0 = fmaxf(mx0, __shfl_xor_sync(0xffffffff, mx0, 2));
            mx1 = fmaxf(mx1, __shfl_xor_sync(0xffffffff, mx1, 1));
            mx1 = fmaxf(mx1, __shfl_xor_sync(0xffffffff, mx1, 2));
            const float mn0 = fmaxf(m0, mx0), mn1 = fmaxf(m1, mx1);
            const float al0 = __expf(m0 - mn0), al1 = __expf(m1 - mn1);
            m0 = mn0; m1 = mn1;

            uint32_t pah[4][4], pal[4][4];
            float rs0 = 0.f, rs1 = 0.f;
#pragma unroll
            for (int f = 0; f < 8; f++) {
                float p0 = __expf(s[f][0] - mn0), p1 = __expf(s[f][1] - mn0);
                float p2 = __expf(s[f][2] - mn1), p3 = __expf(s[f][3] - mn1);
                rs0 += p0 + p1; rs1 += p2 + p3;
                float q0, q1, q2, q3;
                const int ks = f >> 1, hi = (f & 1) * 2;
                pah[ks][hi]     = split_pack_h(p0, p1, q0, q1);
                pah[ks][hi + 1] = split_pack_h(p2, p3, q2, q3);
                pal[ks][hi]     = pack_bf2(__float2bfloat16(q0), __float2bfloat16(q1));
                pal[ks][hi + 1] = pack_bf2(__float2bfloat16(q2), __float2bfloat16(q3));
            }
            rs0 += __shfl_xor_sync(0xffffffff, rs0, 1);
            rs0 += __shfl_xor_sync(0xffffffff, rs0, 2);
            rs1 += __shfl_xor_sync(0xffffffff, rs1, 1);
            rs1 += __shfl_xor_sync(0xffffffff, rs1, 2);
            l0 = l0 * al0 + rs0;
            l1 = l1 * al1 + rs1;

#pragma unroll
            for (int nd = 0; nd < 8; nd++) {
                o[nd][0] *= al0; o[nd][1] *= al0;
                o[nd][2] *= al1; o[nd][3] *= al1;
            }

            // ---- O += P V (3-pass split) ----
#pragma unroll
            for (int ks = 0; ks < 4; ks++) {
                uint32_t vf[4][4];
#pragma unroll
                for (int g = 0; g < 4; g++)
                    ldsm_x4_t(vf[g], st + 2 * AK_B + ((ks * 16 + v_r) * APITCH + g * 16 + v_c) * 2);
#pragma unroll
                for (int nd = 0; nd < 8; nd++)
                    mma16816(o[nd], pah[ks], &vf[nd >> 1][(nd & 1) * 2]);
#pragma unroll
                for (int nd = 0; nd < 8; nd++)
                    mma16816(o[nd], pal[ks], &vf[nd >> 1][(nd & 1) * 2]);
            }
#pragma unroll
            for (int ks = 0; ks < 4; ks++) {
                uint32_t vf[4][4];
#pragma unroll
                for (int g = 0; g < 4; g++)
                    ldsm_x4_t(vf[g], st + 3 * AK_B + ((ks * 16 + v_r) * APITCH + g * 16 + v_c) * 2);
#pragma unroll
                for (int nd = 0; nd < 8; nd++)
                    mma16816(o[nd], pah[ks], &vf[nd >> 1][(nd & 1) * 2]);
            }
        }

        __syncthreads();
        pmload(t + 2);
        issue(t + 2);
    }

    // ---- epilogue: O/l -> split bf16 into g_ah/g_al ----
    const float inv0 = (l0 > 0.f) ? (1.f / l0) : 0.f;
    const float inv1 = (l1 > 0.f) ? (1.f / l1) : 0.f;
    const size_t r0off = (size_t)(b * SEQ + row0) * DM + h * HD;
    const size_t r1off = (size_t)(b * SEQ + row1) * DM + h * HD;
#pragma unroll
    for (int nd = 0; nd < 8; nd++) {
        const int col = nd * 8 + c2;
        float v0 = o[nd][0] * inv0, v1 = o[nd][1] * inv0;
        float v2 = o[nd][2] * inv1, v3 = o[nd][3] * inv1;
        __nv_bfloat16 h0, ll0, h1, ll1, h2, ll2, h3, ll3;
        split2(v0, h0, ll0); split2(v1, h1, ll1);
        split2(v2, h2, ll2); split2(v3, h3, ll3);
        *(uint32_t*)&g_ah[r0off + col] = pack_bf2(h0, h1);
        *(uint32_t*)&g_ah[r1off + col] = pack_bf2(h2, h3);
        *(uint32_t*)&g_al[r0off + col] = pack_bf2(ll0, ll1);
        *(uint32_t*)&g_al[r1off + col] = pack_bf2(ll2, ll3);
    }
}

// ---- Launch ------------------------------------------------------------------------
extern "C" void kernel_launch(void* const* d_in, const int* in_sizes, int n_in,
                              void* d_out, int out_size)
{
    (void)in_sizes; (void)n_in; (void)out_size;
    const float*         x   = (const float*)d_in[0];
    const unsigned char* pad = (const unsigned char*)d_in[1];
    const float*         Wq  = (const float*)d_in[2];
    const float*         Wk  = (const float*)d_in[3];
    const float*         Wv  = (const float*)d_in[4];
    const float*         Wo  = (const float*)d_in[5];
    float*               out = (float*)d_out;

    cudaFuncSetAttribute(qkv_mma_kernel, cudaFuncAttributeMaxDynamicSharedMemorySize, GEMM_SMEM);
    cudaFuncSetAttribute(out_mma_kernel, cudaFuncAttributeMaxDynamicSharedMemorySize, GEMM_SMEM);
    cudaFuncSetAttribute(attn_kernel, cudaFuncAttributeMaxDynamicSharedMemorySize, ATTN_SMEM);

    __nv_bfloat16 *xh, *xl;
    cudaGetSymbolAddress((void**)&xh, g_xh);
    cudaGetSymbolAddress((void**)&xl, g_xl);

    conv_x_kernel<<<MROWS * DM / 4 / 256, 256>>>(x, xh, xl);
    conv_wt_kernel<<<dim3(DM / 32, DM / 32, 4), dim3(32, 8)>>>(Wq, Wk, Wv, Wo);

    qkv_mma_kernel<<<dim3(DM / BN, MROWS / BM, 3), 256, GEMM_SMEM>>>();

    attn_kernel<<<dim3(SEQ / 128, BATCH * NH), 256, ATTN_SMEM>>>(pad);

    out_mma_kernel<<<dim3(DM / BN, MROWS / BM), 256, GEMM_SMEM>>>(out);
}

// round 7
// speedup vs baseline: 3.9885x; 1.0186x over previous
#include <cuda_runtime.h>
#include <cuda_bf16.h>
#include <math_constants.h>
#include <cstdint>

// ---------------------------------------------------------------------------
// MHA Round 7: R6 + single-barrier pipelines (issue-after-sync), 3-stage attn
// ring, heavy-first attention block order, base-2 softmax (log2e folded into
// the Q projection scale).
// ---------------------------------------------------------------------------

#define BATCH 4
#define SEQ   2048
#define DM    1024
#define NH    16
#define HD    64
#define MROWS (BATCH * SEQ)
#define ATT_SCALE 0.125f
#define LOG2E 1.44269504088896340736f

#define BM 128
#define BN 128
#define BK 32
#define NCH (DM / BK)
#define STAGES 3
#define PITCH 40                       // GEMM: 32 data + 8 pad bf16 per row
#define TILE_B (128 * PITCH * 2)       // 10240
#define STAGE_B (4 * TILE_B)
#define GEMM_SMEM (STAGES * STAGE_B)   // 122880

// attention smem: 64-wide tiles, own pitch; 3-stage K/V ring
#define APITCH 72                      // 64 data + 8 pad (row stride 144B)
#define AQ_B   (128 * APITCH * 2)      // 18432 per Q operand (hi or lo)
#define AK_B   (64 * APITCH * 2)       // 9216 per K/V operand tile
#define ASTG_B (4 * AK_B)              // 36864 per stage (Kh,Kl,Vh,Vl)
#define ASTAGES 3
#define AOFF_Q  0
#define AOFF_ST (2 * AQ_B)                   // 36864
#define AOFF_PM (AOFF_ST + ASTAGES * ASTG_B) // 147456
#define ATTN_SMEM (AOFF_PM + 768)            // 148224

// ---- scratch (device globals) -----------------------------------------------
__device__ __align__(256) __nv_bfloat16 g_xh[MROWS * DM];
__device__ __align__(256) __nv_bfloat16 g_xl[MROWS * DM];
__device__ __align__(256) __nv_bfloat16 g_qh[MROWS * DM];
__device__ __align__(256) __nv_bfloat16 g_ql[MROWS * DM];
__device__ __align__(256) __nv_bfloat16 g_kh[MROWS * DM];
__device__ __align__(256) __nv_bfloat16 g_kl[MROWS * DM];
__device__ __align__(256) __nv_bfloat16 g_vh[MROWS * DM];
__device__ __align__(256) __nv_bfloat16 g_vl[MROWS * DM];
__device__ __align__(256) __nv_bfloat16 g_ah[MROWS * DM];
__device__ __align__(256) __nv_bfloat16 g_al[MROWS * DM];
__device__ __align__(256) __nv_bfloat16 g_wth[4][DM * DM];
__device__ __align__(256) __nv_bfloat16 g_wtl[4][DM * DM];

// ---- helpers ------------------------------------------------------------------
__device__ __forceinline__ uint32_t smem_to_u32(const void* p) {
    uint32_t a;
    asm("{ .reg .u64 t; cvta.to.shared.u64 t, %1; cvt.u32.u64 %0, t; }"
        : "=r"(a) : "l"(p));
    return a;
}
__device__ __forceinline__ void mma16816(float* d, const uint32_t* a, const uint32_t* b) {
    asm volatile(
        "mma.sync.aligned.m16n8k16.row.col.f32.bf16.bf16.f32 "
        "{%0,%1,%2,%3}, {%4,%5,%6,%7}, {%8,%9}, {%0,%1,%2,%3};\n"
        : "+f"(d[0]), "+f"(d[1]), "+f"(d[2]), "+f"(d[3])
        : "r"(a[0]), "r"(a[1]), "r"(a[2]), "r"(a[3]), "r"(b[0]), "r"(b[1]));
}
__device__ __forceinline__ void ldsm_x4(uint32_t* r, uint32_t addr) {
    asm volatile("ldmatrix.sync.aligned.m8n8.x4.shared.b16 {%0,%1,%2,%3}, [%4];"
        : "=r"(r[0]), "=r"(r[1]), "=r"(r[2]), "=r"(r[3]) : "r"(addr));
}
__device__ __forceinline__ void ldsm_x4_t(uint32_t* r, uint32_t addr) {
    asm volatile("ldmatrix.sync.aligned.m8n8.x4.trans.shared.b16 {%0,%1,%2,%3}, [%4];"
        : "=r"(r[0]), "=r"(r[1]), "=r"(r[2]), "=r"(r[3]) : "r"(addr));
}
__device__ __forceinline__ void cpasync16(uint32_t dst, const void* src) {
    asm volatile("cp.async.cg.shared.global [%0], [%1], 16;" :: "r"(dst), "l"(src));
}
__device__ __forceinline__ void split2(float v, __nv_bfloat16& h, __nv_bfloat16& l) {
    h = __float2bfloat16(v);
    l = __float2bfloat16(v - __bfloat162float(h));
}
__device__ __forceinline__ uint32_t pack_bf2(__nv_bfloat16 a, __nv_bfloat16 b) {
    __nv_bfloat162 t = __halves2bfloat162(a, b);
    return *(uint32_t*)&t;
}
__device__ __forceinline__ uint32_t split_pack_h(float v0, float v1, float& r0, float& r1) {
    __nv_bfloat16 h0 = __float2bfloat16(v0), h1 = __float2bfloat16(v1);
    r0 = v0 - __bfloat162float(h0);
    r1 = v1 - __bfloat162float(h1);
    return pack_bf2(h0, h1);
}

// ---- GEMM body (MODE 0: fp32 C out; MODE 1: split bf16 out, scaled) ----------
template<int MODE>
__device__ __forceinline__ void gemm_body(
    const __nv_bfloat16* __restrict__ Ah, const __nv_bfloat16* __restrict__ Al,
    const __nv_bfloat16* __restrict__ Bh, const __nv_bfloat16* __restrict__ Bl,
    float* __restrict__ C, __nv_bfloat16* __restrict__ Ch,
    __nv_bfloat16* __restrict__ Cl, float scale)
{
    extern __shared__ char smem[];
    const uint32_t sb = smem_to_u32(smem);
    const int tid  = threadIdx.x;
    const int lane = tid & 31;
    const int wid  = tid >> 5;
    const int wm   = wid >> 2;
    const int wn   = wid & 3;
    const int bm = blockIdx.y, bn = blockIdx.x;

    const __nv_bfloat16* gsrc[4] = {
        Ah + (size_t)bm * BM * DM, Al + (size_t)bm * BM * DM,
        Bh + (size_t)bn * BN * DM, Bl + (size_t)bn * BN * DM
    };

    float acc[4][4][4];
#pragma unroll
    for (int i = 0; i < 4; i++)
#pragma unroll
        for (int j = 0; j < 4; j++)
#pragma unroll
            for (int r = 0; r < 4; r++) acc[i][j][r] = 0.f;

    auto issue = [&](int c) {
        if (c < NCH) {
            const uint32_t sbase = sb + (c % STAGES) * STAGE_B;
            const size_t koff = (size_t)c * BK;
#pragma unroll
            for (int i = 0; i < 8; i++) {
                int q = tid + i * 256;
                int t = q >> 9, r = (q >> 2) & 127, c16 = q & 3;
                cpasync16(sbase + t * TILE_B + (r * PITCH + c16 * 8) * 2,
                          gsrc[t] + (size_t)r * DM + koff + c16 * 8);
            }
        }
        asm volatile("cp.async.commit_group;");
    };

    issue(0); issue(1);

    const int a_r = (lane & 7) + ((lane >> 3) & 1) * 8;
    const int a_c = (lane >> 4) * 8;
    const int b_r = (lane & 7) + ((lane >> 4) & 1) * 8;
    const int b_c = ((lane >> 3) & 1) * 8;

    for (int c = 0; c < NCH; c++) {
        asm volatile("cp.async.wait_group %0;" :: "n"(1));
        __syncthreads();
        issue(c + 2);   // after barrier: stage (c-1)%3 is free for refill

        const uint32_t st = sb + (c % STAGES) * STAGE_B;
        const uint32_t sAh = st, sAl = st + TILE_B, sBh = st + 2 * TILE_B, sBl = st + 3 * TILE_B;

#pragma unroll
        for (int k16 = 0; k16 < 2; k16++) {
            const int kc = k16 * 16;
            uint32_t ah[4][4], al[4][4], bh[2][4], bl[2][4];
#pragma unroll
            for (int mfi = 0; mfi < 4; mfi++)
                ldsm_x4(ah[mfi], sAh + ((wm * 64 + mfi * 16 + a_r) * PITCH + kc + a_c) * 2);
#pragma unroll
            for (int nfp = 0; nfp < 2; nfp++)
                ldsm_x4(bh[nfp], sBh + ((wn * 32 + nfp * 16 + b_r) * PITCH + kc + b_c) * 2);
#pragma unroll
            for (int mfi = 0; mfi < 4; mfi++)
#pragma unroll
                for (int nf = 0; nf < 4; nf++)
                    mma16816(acc[mfi][nf], ah[mfi], &bh[nf >> 1][(nf & 1) * 2]);
#pragma unroll
            for (int nfp = 0; nfp < 2; nfp++)
                ldsm_x4(bl[nfp], sBl + ((wn * 32 + nfp * 16 + b_r) * PITCH + kc + b_c) * 2);
#pragma unroll
            for (int mfi = 0; mfi < 4; mfi++)
#pragma unroll
                for (int nf = 0; nf < 4; nf++)
                    mma16816(acc[mfi][nf], ah[mfi], &bl[nf >> 1][(nf & 1) * 2]);
#pragma unroll
            for (int mfi = 0; mfi < 4; mfi++)
                ldsm_x4(al[mfi], sAl + ((wm * 64 + mfi * 16 + a_r) * PITCH + kc + a_c) * 2);
#pragma unroll
            for (int mfi = 0; mfi < 4; mfi++)
#pragma unroll
                for (int nf = 0; nf < 4; nf++)
                    mma16816(acc[mfi][nf], al[mfi], &bh[nf >> 1][(nf & 1) * 2]);
        }
    }

#pragma unroll
    for (int mfi = 0; mfi < 4; mfi++)
#pragma unroll
        for (int nf = 0; nf < 4; nf++) {
            int row = bm * BM + wm * 64 + mfi * 16 + (lane >> 2);
            int col = bn * BN + wn * 32 + nf * 8 + (lane & 3) * 2;
            if (MODE == 0) {
                *(float2*)&C[(size_t)row * DM + col]       = make_float2(acc[mfi][nf][0], acc[mfi][nf][1]);
                *(float2*)&C[(size_t)(row + 8) * DM + col] = make_float2(acc[mfi][nf][2], acc[mfi][nf][3]);
            } else {
                float v0 = acc[mfi][nf][0] * scale, v1 = acc[mfi][nf][1] * scale;
                float v2 = acc[mfi][nf][2] * scale, v3 = acc[mfi][nf][3] * scale;
                __nv_bfloat16 h0, l0, h1, l1, h2, l2, h3, l3;
                split2(v0, h0, l0); split2(v1, h1, l1);
                split2(v2, h2, l2); split2(v3, h3, l3);
                *(uint32_t*)&Ch[(size_t)row * DM + col]       = pack_bf2(h0, h1);
                *(uint32_t*)&Ch[(size_t)(row + 8) * DM + col] = pack_bf2(h2, h3);
                *(uint32_t*)&Cl[(size_t)row * DM + col]       = pack_bf2(l0, l1);
                *(uint32_t*)&Cl[(size_t)(row + 8) * DM + col] = pack_bf2(l2, l3);
            }
        }
}

__global__ __launch_bounds__(256, 1)
void qkv_mma_kernel()
{
    const int z = blockIdx.z;
    __nv_bfloat16 *Ch, *Cl; float sc;
    if (z == 0)      { Ch = g_qh; Cl = g_ql; sc = ATT_SCALE * LOG2E; }  // base-2 softmax
    else if (z == 1) { Ch = g_kh; Cl = g_kl; sc = 1.f; }
    else             { Ch = g_vh; Cl = g_vl; sc = 1.f; }
    gemm_body<1>(g_xh, g_xl, g_wth[z], g_wtl[z], nullptr, Ch, Cl, sc);
}
__global__ __launch_bounds__(256, 1)
void out_mma_kernel(float* __restrict__ out)
{
    gemm_body<0>(g_ah, g_al, g_wth[3], g_wtl[3], out, nullptr, nullptr, 1.f);
}

// ---- conversion kernels ---------------------------------------------------------
__global__ __launch_bounds__(256) void conv_x_kernel(const float* __restrict__ s,
                                                     __nv_bfloat16* __restrict__ dh,
                                                     __nv_bfloat16* __restrict__ dl) {
    int i = blockIdx.x * 256 + threadIdx.x;
    float4 v = ((const float4*)s)[i];
    __nv_bfloat16 h0,h1,h2,h3,l0,l1,l2,l3;
    split2(v.x,h0,l0); split2(v.y,h1,l1); split2(v.z,h2,l2); split2(v.w,h3,l3);
    ((uint32_t*)dh)[i*2+0] = pack_bf2(h0,h1);
    ((uint32_t*)dh)[i*2+1] = pack_bf2(h2,h3);
    ((uint32_t*)dl)[i*2+0] = pack_bf2(l0,l1);
    ((uint32_t*)dl)[i*2+1] = pack_bf2(l2,l3);
}
__global__ __launch_bounds__(256) void conv_wt_kernel(const float* __restrict__ W0,
                                                      const float* __restrict__ W1,
                                                      const float* __restrict__ W2,
                                                      const float* __restrict__ W3) {
    __shared__ float tile[32][33];
    const int z = blockIdx.z;
    const float* W = (z == 0) ? W0 : (z == 1) ? W1 : (z == 2) ? W2 : W3;
    const int n0 = blockIdx.x * 32, k0 = blockIdx.y * 32;
    const int tx = threadIdx.x, ty = threadIdx.y;
#pragma unroll
    for (int i = ty; i < 32; i += 8)
        tile[i][tx] = W[(size_t)(k0 + i) * DM + n0 + tx];
    __syncthreads();
#pragma unroll
    for (int i = ty; i < 32; i += 8) {
        float v = tile[tx][i];
        __nv_bfloat16 h, l; split2(v, h, l);
        g_wth[z][(size_t)(n0 + i) * DM + k0 + tx] = h;
        g_wtl[z][(size_t)(n0 + i) * DM + k0 + tx] = l;
    }
}

// ---- Flash attention on tensor cores (base-2 softmax) -----------------------------
__global__ __launch_bounds__(256, 1)
void attn_kernel(const unsigned char* __restrict__ pad)
{
    extern __shared__ char smem[];
    const uint32_t sb = smem_to_u32(smem);
    const int tid = threadIdx.x, lane = tid & 31, wq = tid >> 5;
    const int b = blockIdx.y >> 4, h = blockIdx.y & 15;
    const int bx = (gridDim.x - 1) - blockIdx.x;   // heavy blocks first
    const int qbase = bx * 128;
    const int ntiles = bx * 2 + 2;

    // ---- Q tile load (bundled into commit group 0 with stage 0) ----
    {
        const __nv_bfloat16* srcq[2] = {
            g_qh + (size_t)(b * SEQ + qbase) * DM + h * HD,
            g_ql + (size_t)(b * SEQ + qbase) * DM + h * HD };
#pragma unroll
        for (int i = 0; i < 8; i++) {
            int q = tid + i * 256;
            int op = q >> 10, row = (q >> 3) & 127, ch = q & 7;
            cpasync16(sb + AOFF_Q + op * AQ_B + (row * APITCH + ch * 8) * 2,
                      srcq[op] + (size_t)row * DM + ch * 8);
        }
    }

    auto issue = [&](int t) {
        if (t < ntiles) {
            const int k0 = t * 64;
            const uint32_t sbase = sb + AOFF_ST + (t % ASTAGES) * ASTG_B;
            const __nv_bfloat16* gs[4] = {
                g_kh + (size_t)(b * SEQ + k0) * DM + h * HD,
                g_kl + (size_t)(b * SEQ + k0) * DM + h * HD,
                g_vh + (size_t)(b * SEQ + k0) * DM + h * HD,
                g_vl + (size_t)(b * SEQ + k0) * DM + h * HD };
#pragma unroll
            for (int i = 0; i < 8; i++) {
                int q = tid + i * 256;
                int tt = q >> 9, row = (q >> 3) & 63, ch = q & 7;
                cpasync16(sbase + tt * AK_B + (row * APITCH + ch * 8) * 2,
                          gs[tt] + (size_t)row * DM + ch * 8);
            }
        }
        asm volatile("cp.async.commit_group;");
    };
    auto pmload = [&](int t) {
        if (t < ntiles && tid < 64) {
            float v = pad[b * SEQ + t * 64 + tid] ? -CUDART_INF_F : 0.f;
            *(float*)(smem + AOFF_PM + (t % ASTAGES) * 256 + tid * 4) = v;
        }
    };

    pmload(0); issue(0);
    pmload(1); issue(1);

    const int r  = lane >> 2;
    const int c2 = (lane & 3) * 2;
    const int row0 = qbase + wq * 16 + r;
    const int row1 = row0 + 8;
    const int qmax = qbase + wq * 16 + 15;

    const int a_r = (lane & 7) + ((lane >> 3) & 1) * 8;
    const int a_c = (lane >> 4) * 8;
    const int b_r = (lane & 7) + ((lane >> 4) & 1) * 8;   // K non-trans
    const int b_c = ((lane >> 3) & 1) * 8;
    const int v_r = (lane & 7) + ((lane >> 3) & 1) * 8;   // V trans
    const int v_c = (lane >> 4) * 8;

    float m0 = -CUDART_INF_F, m1 = -CUDART_INF_F, l0 = 0.f, l1 = 0.f;
    float o[8][4];
#pragma unroll
    for (int i = 0; i < 8; i++)
#pragma unroll
        for (int j = 0; j < 4; j++) o[i][j] = 0.f;

    uint32_t qfh[4][4], qfl[4][4];

    for (int t = 0; t < ntiles; t++) {
        asm volatile("cp.async.wait_group %0;" :: "n"(1));
        __syncthreads();

        if (t == 0) {
#pragma unroll
            for (int dk = 0; dk < 4; dk++) {
                ldsm_x4(qfh[dk], sb + AOFF_Q +        ((wq * 16 + a_r) * APITCH + dk * 16 + a_c) * 2);
                ldsm_x4(qfl[dk], sb + AOFF_Q + AQ_B + ((wq * 16 + a_r) * APITCH + dk * 16 + a_c) * 2);
            }
        }
        pmload(t + 2);
        issue(t + 2);   // refills ring slot (t-1)%3, free after this barrier

        const int k0 = t * 64;
        if (k0 <= qmax) {
            const uint32_t st = sb + AOFF_ST + (t % ASTAGES) * ASTG_B;
            // ---- S = Q K^T (3-pass split) ----
            float s[8][4];
#pragma unroll
            for (int f = 0; f < 8; f++)
#pragma unroll
                for (int j = 0; j < 4; j++) s[f][j] = 0.f;

#pragma unroll
            for (int dk = 0; dk < 4; dk++) {
                uint32_t kf[4][4];
#pragma unroll
                for (int g = 0; g < 4; g++)
                    ldsm_x4(kf[g], st + ((g * 16 + b_r) * APITCH + dk * 16 + b_c) * 2);
#pragma unroll
                for (int f = 0; f < 8; f++)
                    mma16816(s[f], qfh[dk], &kf[f >> 1][(f & 1) * 2]);
#pragma unroll
                for (int f = 0; f < 8; f++)
                    mma16816(s[f], qfl[dk], &kf[f >> 1][(f & 1) * 2]);
            }
#pragma unroll
            for (int dk = 0; dk < 4; dk++) {
                uint32_t kf[4][4];
#pragma unroll
                for (int g = 0; g < 4; g++)
                    ldsm_x4(kf[g], st + AK_B + ((g * 16 + b_r) * APITCH + dk * 16 + b_c) * 2);
#pragma unroll
                for (int f = 0; f < 8; f++)
                    mma16816(s[f], qfh[dk], &kf[f >> 1][(f & 1) * 2]);
            }

            // ---- masks ----
            const bool needc = (k0 + 63 > row0);
#pragma unroll
            for (int f = 0; f < 8; f++) {
                float2 pmv = *(float2*)(smem + AOFF_PM + (t % ASTAGES) * 256 + (f * 8 + c2) * 4);
                s[f][0] += pmv.x; s[f][1] += pmv.y;
                s[f][2] += pmv.x; s[f][3] += pmv.y;
                if (needc) {
                    int k = k0 + f * 8 + c2;
                    if (k     > row0) s[f][0] = -CUDART_INF_F;
                    if (k + 1 > row0) s[f][1] = -CUDART_INF_F;
                    if (k     > row1) s[f][2] = -CUDART_INF_F;
                    if (k + 1 > row1) s[f][3] = -CUDART_INF_F;
                }
            }

            // ---- online softmax (base 2: log2e pre-folded into Q) ----
            float mx0 = -CUDART_INF_F, mx1 = -CUDART_INF_F;
#pragma unroll
            for (int f = 0; f < 8; f++) {
                mx0 = fmaxf(mx0, fmaxf(s[f][0], s[f][1]));
                mx1 = fmaxf(mx1, fmaxf(s[f][2], s[f][3]));
            }
            mx0 = fmaxf(mx0, __shfl_xor_sync(0xffffffff, mx0, 1));
            mx0 = fmaxf(mx0, __shfl_xor_sync(0xffffffff, mx0, 2));
            mx1 = fmaxf(mx1, __shfl_xor_sync(0xffffffff, mx1, 1));
            mx1 = fmaxf(mx1, __shfl_xor_sync(0xffffffff, mx1, 2));
            const float mn0 = fmaxf(m0, mx0), mn1 = fmaxf(m1, mx1);
            const float al0 = exp2f(m0 - mn0), al1 = exp2f(m1 - mn1);
            m0 = mn0; m1 = mn1;

            uint32_t pah[4][4], pal[4][4];
            float rs0 = 0.f, rs1 = 0.f;
#pragma unroll
            for (int f = 0; f < 8; f++) {
                float p0 = exp2f(s[f][0] - mn0), p1 = exp2f(s[f][1] - mn0);
                float p2 = exp2f(s[f][2] - mn1), p3 = exp2f(s[f][3] - mn1);
                rs0 += p0 + p1; rs1 += p2 + p3;
                float q0, q1, q2, q3;
                const int ks = f >> 1, hi = (f & 1) * 2;
                pah[ks][hi]     = split_pack_h(p0, p1, q0, q1);
                pah[ks][hi + 1] = split_pack_h(p2, p3, q2, q3);
                pal[ks][hi]     = pack_bf2(__float2bfloat16(q0), __float2bfloat16(q1));
                pal[ks][hi + 1] = pack_bf2(__float2bfloat16(q2), __float2bfloat16(q3));
            }
            rs0 += __shfl_xor_sync(0xffffffff, rs0, 1);
            rs0 += __shfl_xor_sync(0xffffffff, rs0, 2);
            rs1 += __shfl_xor_sync(0xffffffff, rs1, 1);
            rs1 += __shfl_xor_sync(0xffffffff, rs1, 2);
            l0 = l0 * al0 + rs0;
            l1 = l1 * al1 + rs1;

#pragma unroll
            for (int nd = 0; nd < 8; nd++) {
                o[nd][0] *= al0; o[nd][1] *= al0;
                o[nd][2] *= al1; o[nd][3] *= al1;
            }

            // ---- O += P V (3-pass split) ----
#pragma unroll
            for (int ks = 0; ks < 4; ks++) {
                uint32_t vf[4][4];
#pragma unroll
                for (int g = 0; g < 4; g++)
                    ldsm_x4_t(vf[g], st + 2 * AK_B + ((ks * 16 + v_r) * APITCH + g * 16 + v_c) * 2);
#pragma unroll
                for (int nd = 0; nd < 8; nd++)
                    mma16816(o[nd], pah[ks], &vf[nd >> 1][(nd & 1) * 2]);
#pragma unroll
                for (int nd = 0; nd < 8; nd++)
                    mma16816(o[nd], pal[ks], &vf[nd >> 1][(nd & 1) * 2]);
            }
#pragma unroll
            for (int ks = 0; ks < 4; ks++) {
                uint32_t vf[4][4];
#pragma unroll
                for (int g = 0; g < 4; g++)
                    ldsm_x4_t(vf[g], st + 3 * AK_B + ((ks * 16 + v_r) * APITCH + g * 16 + v_c) * 2);
#pragma unroll
                for (int nd = 0; nd < 8; nd++)
                    mma16816(o[nd], pah[ks], &vf[nd >> 1][(nd & 1) * 2]);
            }
        }
    }

    // ---- epilogue: O/l -> split bf16 into g_ah/g_al ----
    const float inv0 = (l0 > 0.f) ? (1.f / l0) : 0.f;
    const float inv1 = (l1 > 0.f) ? (1.f / l1) : 0.f;
    const size_t r0off = (size_t)(b * SEQ + row0) * DM + h * HD;
    const size_t r1off = (size_t)(b * SEQ + row1) * DM + h * HD;
#pragma unroll
    for (int nd = 0; nd < 8; nd++) {
        const int col = nd * 8 + c2;
        float v0 = o[nd][0] * inv0, v1 = o[nd][1] * inv0;
        float v2 = o[nd][2] * inv1, v3 = o[nd][3] * inv1;
        __nv_bfloat16 h0, ll0, h1, ll1, h2, ll2, h3, ll3;
        split2(v0, h0, ll0); split2(v1, h1, ll1);
        split2(v2, h2, ll2); split2(v3, h3, ll3);
        *(uint32_t*)&g_ah[r0off + col] = pack_bf2(h0, h1);
        *(uint32_t*)&g_ah[r1off + col] = pack_bf2(h2, h3);
        *(uint32_t*)&g_al[r0off + col] = pack_bf2(ll0, ll1);
        *(uint32_t*)&g_al[r1off + col] = pack_bf2(ll2, ll3);
    }
}

// ---- Launch ------------------------------------------------------------------------
extern "C" void kernel_launch(void* const* d_in, const int* in_sizes, int n_in,
                              void* d_out, int out_size)
{
    (void)in_sizes; (void)n_in; (void)out_size;
    const float*         x   = (const float*)d_in[0];
    const unsigned char* pad = (const unsigned char*)d_in[1];
    const float*         Wq  = (const float*)d_in[2];
    const float*         Wk  = (const float*)d_in[3];
    const float*         Wv  = (const float*)d_in[4];
    const float*         Wo  = (const float*)d_in[5];
    float*               out = (float*)d_out;

    cudaFuncSetAttribute(qkv_mma_kernel, cudaFuncAttributeMaxDynamicSharedMemorySize, GEMM_SMEM);
    cudaFuncSetAttribute(out_mma_kernel, cudaFuncAttributeMaxDynamicSharedMemorySize, GEMM_SMEM);
    cudaFuncSetAttribute(attn_kernel, cudaFuncAttributeMaxDynamicSharedMemorySize, ATTN_SMEM);

    __nv_bfloat16 *xh, *xl;
    cudaGetSymbolAddress((void**)&xh, g_xh);
    cudaGetSymbolAddress((void**)&xl, g_xl);

    conv_x_kernel<<<MROWS * DM / 4 / 256, 256>>>(x, xh, xl);
    conv_wt_kernel<<<dim3(DM / 32, DM / 32, 4), dim3(32, 8)>>>(Wq, Wk, Wv, Wo);

    qkv_mma_kernel<<<dim3(DM / BN, MROWS / BM, 3), 256, GEMM_SMEM>>>();

    attn_kernel<<<dim3(SEQ / 128, BATCH * NH), 256, ATTN_SMEM>>>(pad);

    out_mma_kernel<<<dim3(DM / BN, MROWS / BM), 256, GEMM_SMEM>>>(out);
}

// round 8
// speedup vs baseline: 5.1024x; 1.2793x over previous
#include <cuda_runtime.h>
#include <cuda_bf16.h>
#include <cuda_fp16.h>
#include <math_constants.h>
#include <cstdint>

// ---------------------------------------------------------------------------
// MHA Round 8: fp16 arithmetic where 11-bit mantissa suffices.
//  qkv : (xh+xl)fp16 @ Wfp16, 2-pass  -> Q split-fp16 (scaled), K,V single fp16
//  attn: QK = (qh+ql)·K 2-pass; PV = (ph+pl)·V 2-pass; A -> split bf16
//  out : bf16 3-pass (A split, Wo split) — error-critical last stage
// ---------------------------------------------------------------------------

#define BATCH 4
#define SEQ   2048
#define DM    1024
#define NH    16
#define HD    64
#define MROWS (BATCH * SEQ)
#define ATT_SCALE 0.125f
#define LOG2E 1.44269504088896340736f

#define BM 128
#define BN 128
#define BK 32
#define NCH (DM / BK)
#define STAGES 3
#define PITCH 40
#define TILE_B (128 * PITCH * 2)       // 10240

// attention smem
#define APITCH 72
#define AQ_B   (128 * APITCH * 2)      // 18432 per Q operand
#define AK_B   (64 * APITCH * 2)       // 9216 per K/V tile
#define ASTG_B (2 * AK_B)              // 18432 per stage (K, V)
#define ASTAGES 3
#define AOFF_Q  0
#define AOFF_ST (2 * AQ_B)                   // 36864
#define AOFF_PM (AOFF_ST + ASTAGES * ASTG_B) // 92160
#define ATTN_SMEM (AOFF_PM + 768)            // 92928

// ---- scratch ----------------------------------------------------------------
__device__ __align__(256) __half g_xh[MROWS * DM];
__device__ __align__(256) __half g_xl[MROWS * DM];
__device__ __align__(256) __half g_qh[MROWS * DM];
__device__ __align__(256) __half g_ql[MROWS * DM];
__device__ __align__(256) __half g_k [MROWS * DM];
__device__ __align__(256) __half g_v [MROWS * DM];
__device__ __align__(256) __nv_bfloat16 g_ah[MROWS * DM];
__device__ __align__(256) __nv_bfloat16 g_al[MROWS * DM];
__device__ __align__(256) __half g_wf[3][DM * DM];        // W^T fp16: q,k,v
__device__ __align__(256) __nv_bfloat16 g_woh[DM * DM];   // Wo^T bf16 hi
__device__ __align__(256) __nv_bfloat16 g_wol[DM * DM];   // Wo^T bf16 lo

// ---- helpers ------------------------------------------------------------------
__device__ __forceinline__ uint32_t smem_to_u32(const void* p) {
    uint32_t a;
    asm("{ .reg .u64 t; cvta.to.shared.u64 t, %1; cvt.u32.u64 %0, t; }"
        : "=r"(a) : "l"(p));
    return a;
}
__device__ __forceinline__ void mma_bf16(float* d, const uint32_t* a, const uint32_t* b) {
    asm volatile(
        "mma.sync.aligned.m16n8k16.row.col.f32.bf16.bf16.f32 "
        "{%0,%1,%2,%3}, {%4,%5,%6,%7}, {%8,%9}, {%0,%1,%2,%3};\n"
        : "+f"(d[0]), "+f"(d[1]), "+f"(d[2]), "+f"(d[3])
        : "r"(a[0]), "r"(a[1]), "r"(a[2]), "r"(a[3]), "r"(b[0]), "r"(b[1]));
}
__device__ __forceinline__ void mma_f16(float* d, const uint32_t* a, const uint32_t* b) {
    asm volatile(
        "mma.sync.aligned.m16n8k16.row.col.f32.f16.f16.f32 "
        "{%0,%1,%2,%3}, {%4,%5,%6,%7}, {%8,%9}, {%0,%1,%2,%3};\n"
        : "+f"(d[0]), "+f"(d[1]), "+f"(d[2]), "+f"(d[3])
        : "r"(a[0]), "r"(a[1]), "r"(a[2]), "r"(a[3]), "r"(b[0]), "r"(b[1]));
}
template<int PREC>
__device__ __forceinline__ void mma_p(float* d, const uint32_t* a, const uint32_t* b) {
    if (PREC == 0) mma_bf16(d, a, b); else mma_f16(d, a, b);
}
__device__ __forceinline__ void ldsm_x4(uint32_t* r, uint32_t addr) {
    asm volatile("ldmatrix.sync.aligned.m8n8.x4.shared.b16 {%0,%1,%2,%3}, [%4];"
        : "=r"(r[0]), "=r"(r[1]), "=r"(r[2]), "=r"(r[3]) : "r"(addr));
}
__device__ __forceinline__ void ldsm_x4_t(uint32_t* r, uint32_t addr) {
    asm volatile("ldmatrix.sync.aligned.m8n8.x4.trans.shared.b16 {%0,%1,%2,%3}, [%4];"
        : "=r"(r[0]), "=r"(r[1]), "=r"(r[2]), "=r"(r[3]) : "r"(addr));
}
__device__ __forceinline__ void cpasync16(uint32_t dst, const void* src) {
    asm volatile("cp.async.cg.shared.global [%0], [%1], 16;" :: "r"(dst), "l"(src));
}
// bf16 split
__device__ __forceinline__ void split2(float v, __nv_bfloat16& h, __nv_bfloat16& l) {
    h = __float2bfloat16(v);
    l = __float2bfloat16(v - __bfloat162float(h));
}
__device__ __forceinline__ uint32_t pack_bf2(__nv_bfloat16 a, __nv_bfloat16 b) {
    __nv_bfloat162 t = __halves2bfloat162(a, b);
    return *(uint32_t*)&t;
}
// fp16 split
__device__ __forceinline__ void split2h(float v, __half& h, __half& l) {
    h = __float2half_rn(v);
    l = __float2half_rn(v - __half2float(h));
}
__device__ __forceinline__ uint32_t pack_h2(__half a, __half b) {
    __half2 t = __halves2half2(a, b);
    return *(uint32_t*)&t;
}
__device__ __forceinline__ uint32_t split_pack_hh(float v0, float v1, float& r0, float& r1) {
    __half h0 = __float2half_rn(v0), h1 = __float2half_rn(v1);
    r0 = v0 - __half2float(h0);
    r1 = v1 - __half2float(h1);
    return pack_h2(h0, h1);
}

// ---- GEMM body ------------------------------------------------------------------
// PREC: 0 bf16, 1 fp16. BPASS: 1 (B single) or 2 (B split).
// OMODE: 0 fp32 C; 1 split-fp16 (Ch,Cl) scaled; 2 single-fp16 (Ch) scaled.
template<int PREC, int BPASS, int OMODE>
__device__ __forceinline__ void gemm_body(
    const void* Ah_, const void* Al_, const void* Bh_, const void* Bl_,
    float* __restrict__ C, __half* __restrict__ Ch, __half* __restrict__ Cl,
    float scale)
{
    constexpr int NT = BPASS + 2;                 // tiles per stage
    constexpr int STAGE_B = NT * TILE_B;
    extern __shared__ char smem[];
    const uint32_t sb = smem_to_u32(smem);
    const int tid  = threadIdx.x;
    const int lane = tid & 31;
    const int wid  = tid >> 5;
    const int wm   = wid >> 2;
    const int wn   = wid & 3;
    const int bm = blockIdx.y, bn = blockIdx.x;

    const char* gsrc[NT];
    gsrc[0] = (const char*)Ah_ + (size_t)bm * BM * DM * 2;
    gsrc[1] = (const char*)Al_ + (size_t)bm * BM * DM * 2;
    gsrc[2] = (const char*)Bh_ + (size_t)bn * BN * DM * 2;
    if (BPASS == 2) gsrc[3] = (const char*)Bl_ + (size_t)bn * BN * DM * 2;

    float acc[4][4][4];
#pragma unroll
    for (int i = 0; i < 4; i++)
#pragma unroll
        for (int j = 0; j < 4; j++)
#pragma unroll
            for (int r = 0; r < 4; r++) acc[i][j][r] = 0.f;

    auto issue = [&](int c) {
        if (c < NCH) {
            const uint32_t sbase = sb + (c % STAGES) * STAGE_B;
            const size_t koff = (size_t)c * BK * 2;
#pragma unroll
            for (int i = 0; i < 2 * NT; i++) {
                int q = tid + i * 256;
                int t = q >> 9, r = (q >> 2) & 127, c16 = q & 3;
                cpasync16(sbase + t * TILE_B + (r * PITCH + c16 * 8) * 2,
                          gsrc[t] + (size_t)r * DM * 2 + koff + c16 * 16);
            }
        }
        asm volatile("cp.async.commit_group;");
    };

    issue(0); issue(1);

    const int a_r = (lane & 7) + ((lane >> 3) & 1) * 8;
    const int a_c = (lane >> 4) * 8;
    const int b_r = (lane & 7) + ((lane >> 4) & 1) * 8;
    const int b_c = ((lane >> 3) & 1) * 8;

    for (int c = 0; c < NCH; c++) {
        asm volatile("cp.async.wait_group %0;" :: "n"(1));
        __syncthreads();
        issue(c + 2);

        const uint32_t st = sb + (c % STAGES) * STAGE_B;
        const uint32_t sAh = st, sAl = st + TILE_B, sBh = st + 2 * TILE_B;
        const uint32_t sBl = st + 3 * TILE_B;

#pragma unroll
        for (int k16 = 0; k16 < 2; k16++) {
            const int kc = k16 * 16;
            uint32_t ah[4][4], al[4][4], bh[2][4], bl[2][4];
#pragma unroll
            for (int mfi = 0; mfi < 4; mfi++)
                ldsm_x4(ah[mfi], sAh + ((wm * 64 + mfi * 16 + a_r) * PITCH + kc + a_c) * 2);
#pragma unroll
            for (int nfp = 0; nfp < 2; nfp++)
                ldsm_x4(bh[nfp], sBh + ((wn * 32 + nfp * 16 + b_r) * PITCH + kc + b_c) * 2);
#pragma unroll
            for (int mfi = 0; mfi < 4; mfi++)
#pragma unroll
                for (int nf = 0; nf < 4; nf++)
                    mma_p<PREC>(acc[mfi][nf], ah[mfi], &bh[nf >> 1][(nf & 1) * 2]);
            if (BPASS == 2) {
#pragma unroll
                for (int nfp = 0; nfp < 2; nfp++)
                    ldsm_x4(bl[nfp], sBl + ((wn * 32 + nfp * 16 + b_r) * PITCH + kc + b_c) * 2);
#pragma unroll
                for (int mfi = 0; mfi < 4; mfi++)
#pragma unroll
                    for (int nf = 0; nf < 4; nf++)
                        mma_p<PREC>(acc[mfi][nf], ah[mfi], &bl[nf >> 1][(nf & 1) * 2]);
            }
#pragma unroll
            for (int mfi = 0; mfi < 4; mfi++)
                ldsm_x4(al[mfi], sAl + ((wm * 64 + mfi * 16 + a_r) * PITCH + kc + a_c) * 2);
#pragma unroll
            for (int mfi = 0; mfi < 4; mfi++)
#pragma unroll
                for (int nf = 0; nf < 4; nf++)
                    mma_p<PREC>(acc[mfi][nf], al[mfi], &bh[nf >> 1][(nf & 1) * 2]);
        }
    }

#pragma unroll
    for (int mfi = 0; mfi < 4; mfi++)
#pragma unroll
        for (int nf = 0; nf < 4; nf++) {
            int row = bm * BM + wm * 64 + mfi * 16 + (lane >> 2);
            int col = bn * BN + wn * 32 + nf * 8 + (lane & 3) * 2;
            float v0 = acc[mfi][nf][0] * scale, v1 = acc[mfi][nf][1] * scale;
            float v2 = acc[mfi][nf][2] * scale, v3 = acc[mfi][nf][3] * scale;
            if (OMODE == 0) {
                *(float2*)&C[(size_t)row * DM + col]       = make_float2(v0, v1);
                *(float2*)&C[(size_t)(row + 8) * DM + col] = make_float2(v2, v3);
            } else if (OMODE == 1) {
                __half h0, l0, h1, l1, h2, l2, h3, l3;
                split2h(v0, h0, l0); split2h(v1, h1, l1);
                split2h(v2, h2, l2); split2h(v3, h3, l3);
                *(uint32_t*)&Ch[(size_t)row * DM + col]       = pack_h2(h0, h1);
                *(uint32_t*)&Ch[(size_t)(row + 8) * DM + col] = pack_h2(h2, h3);
                *(uint32_t*)&Cl[(size_t)row * DM + col]       = pack_h2(l0, l1);
                *(uint32_t*)&Cl[(size_t)(row + 8) * DM + col] = pack_h2(l2, l3);
            } else {
                *(uint32_t*)&Ch[(size_t)row * DM + col] =
                    pack_h2(__float2half_rn(v0), __float2half_rn(v1));
                *(uint32_t*)&Ch[(size_t)(row + 8) * DM + col] =
                    pack_h2(__float2half_rn(v2), __float2half_rn(v3));
            }
        }
}

__global__ __launch_bounds__(256, 1)
void qkv_mma_kernel()
{
    const int z = blockIdx.z;
    if (z == 0)
        gemm_body<1, 1, 1>(g_xh, g_xl, g_wf[0], nullptr,
                           nullptr, g_qh, g_ql, ATT_SCALE * LOG2E);
    else if (z == 1)
        gemm_body<1, 1, 2>(g_xh, g_xl, g_wf[1], nullptr,
                           nullptr, g_k, nullptr, 1.f);
    else
        gemm_body<1, 1, 2>(g_xh, g_xl, g_wf[2], nullptr,
                           nullptr, g_v, nullptr, 1.f);
}
__global__ __launch_bounds__(256, 1)
void out_mma_kernel(float* __restrict__ out)
{
    gemm_body<0, 2, 0>(g_ah, g_al, g_woh, g_wol, out, nullptr, nullptr, 1.f);
}

// ---- conversions --------------------------------------------------------------
__global__ __launch_bounds__(256) void conv_x_kernel(const float* __restrict__ s) {
    int i = blockIdx.x * 256 + threadIdx.x;
    float4 v = ((const float4*)s)[i];
    __half h0,h1,h2,h3,l0,l1,l2,l3;
    split2h(v.x,h0,l0); split2h(v.y,h1,l1); split2h(v.z,h2,l2); split2h(v.w,h3,l3);
    ((uint32_t*)g_xh)[i*2+0] = pack_h2(h0,h1);
    ((uint32_t*)g_xh)[i*2+1] = pack_h2(h2,h3);
    ((uint32_t*)g_xl)[i*2+0] = pack_h2(l0,l1);
    ((uint32_t*)g_xl)[i*2+1] = pack_h2(l2,l3);
}
__global__ __launch_bounds__(256) void conv_wt_kernel(const float* __restrict__ W0,
                                                      const float* __restrict__ W1,
                                                      const float* __restrict__ W2,
                                                      const float* __restrict__ W3) {
    __shared__ float tile[32][33];
    const int z = blockIdx.z;
    const float* W = (z == 0) ? W0 : (z == 1) ? W1 : (z == 2) ? W2 : W3;
    const int n0 = blockIdx.x * 32, k0 = blockIdx.y * 32;
    const int tx = threadIdx.x, ty = threadIdx.y;
#pragma unroll
    for (int i = ty; i < 32; i += 8)
        tile[i][tx] = W[(size_t)(k0 + i) * DM + n0 + tx];
    __syncthreads();
#pragma unroll
    for (int i = ty; i < 32; i += 8) {
        float v = tile[tx][i];
        size_t idx = (size_t)(n0 + i) * DM + k0 + tx;
        if (z < 3) {
            g_wf[z][idx] = __float2half_rn(v);
        } else {
            __nv_bfloat16 h, l; split2(v, h, l);
            g_woh[idx] = h; g_wol[idx] = l;
        }
    }
}

// ---- Flash attention (fp16 operands, base-2 softmax) ----------------------------
__global__ __launch_bounds__(256, 1)
void attn_kernel(const unsigned char* __restrict__ pad)
{
    extern __shared__ char smem[];
    const uint32_t sb = smem_to_u32(smem);
    const int tid = threadIdx.x, lane = tid & 31, wq = tid >> 5;
    const int b = blockIdx.y >> 4, h = blockIdx.y & 15;
    const int bx = (gridDim.x - 1) - blockIdx.x;   // heavy blocks first
    const int qbase = bx * 128;
    const int ntiles = bx * 2 + 2;

    // Q (qh, ql) load — bundled into commit group 0
    {
        const __half* srcq[2] = {
            g_qh + (size_t)(b * SEQ + qbase) * DM + h * HD,
            g_ql + (size_t)(b * SEQ + qbase) * DM + h * HD };
#pragma unroll
        for (int i = 0; i < 8; i++) {
            int q = tid + i * 256;
            int op = q >> 10, row = (q >> 3) & 127, ch = q & 7;
            cpasync16(sb + AOFF_Q + op * AQ_B + (row * APITCH + ch * 8) * 2,
                      srcq[op] + (size_t)row * DM + ch * 8);
        }
    }

    auto issue = [&](int t) {
        if (t < ntiles) {
            const int k0 = t * 64;
            const uint32_t sbase = sb + AOFF_ST + (t % ASTAGES) * ASTG_B;
            const __half* gs[2] = {
                g_k + (size_t)(b * SEQ + k0) * DM + h * HD,
                g_v + (size_t)(b * SEQ + k0) * DM + h * HD };
#pragma unroll
            for (int i = 0; i < 4; i++) {
                int q = tid + i * 256;
                int tt = q >> 9, row = (q >> 3) & 63, ch = q & 7;
                cpasync16(sbase + tt * AK_B + (row * APITCH + ch * 8) * 2,
                          gs[tt] + (size_t)row * DM + ch * 8);
            }
        }
        asm volatile("cp.async.commit_group;");
    };
    auto pmload = [&](int t) {
        if (t < ntiles && tid < 64) {
            float v = pad[b * SEQ + t * 64 + tid] ? -CUDART_INF_F : 0.f;
            *(float*)(smem + AOFF_PM + (t % ASTAGES) * 256 + tid * 4) = v;
        }
    };

    pmload(0); issue(0);
    pmload(1); issue(1);

    const int r  = lane >> 2;
    const int c2 = (lane & 3) * 2;
    const int row0 = qbase + wq * 16 + r;
    const int row1 = row0 + 8;
    const int qmax = qbase + wq * 16 + 15;

    const int a_r = (lane & 7) + ((lane >> 3) & 1) * 8;
    const int a_c = (lane >> 4) * 8;
    const int b_r = (lane & 7) + ((lane >> 4) & 1) * 8;
    const int b_c = ((lane >> 3) & 1) * 8;
    const int v_r = (lane & 7) + ((lane >> 3) & 1) * 8;
    const int v_c = (lane >> 4) * 8;

    float m0 = -CUDART_INF_F, m1 = -CUDART_INF_F, l0 = 0.f, l1 = 0.f;
    float o[8][4];
#pragma unroll
    for (int i = 0; i < 8; i++)
#pragma unroll
        for (int j = 0; j < 4; j++) o[i][j] = 0.f;

    uint32_t qfh[4][4], qfl[4][4];

    for (int t = 0; t < ntiles; t++) {
        asm volatile("cp.async.wait_group %0;" :: "n"(1));
        __syncthreads();

        if (t == 0) {
#pragma unroll
            for (int dk = 0; dk < 4; dk++) {
                ldsm_x4(qfh[dk], sb + AOFF_Q +        ((wq * 16 + a_r) * APITCH + dk * 16 + a_c) * 2);
                ldsm_x4(qfl[dk], sb + AOFF_Q + AQ_B + ((wq * 16 + a_r) * APITCH + dk * 16 + a_c) * 2);
            }
        }
        pmload(t + 2);
        issue(t + 2);

        const int k0 = t * 64;
        if (k0 <= qmax) {
            const uint32_t st = sb + AOFF_ST + (t % ASTAGES) * ASTG_B;
            // ---- S = (qh+ql) K^T, 2-pass fp16 ----
            float s[8][4];
#pragma unroll
            for (int f = 0; f < 8; f++)
#pragma unroll
                for (int j = 0; j < 4; j++) s[f][j] = 0.f;

#pragma unroll
            for (int dk = 0; dk < 4; dk++) {
                uint32_t kf[4][4];
#pragma unroll
                for (int g = 0; g < 4; g++)
                    ldsm_x4(kf[g], st + ((g * 16 + b_r) * APITCH + dk * 16 + b_c) * 2);
#pragma unroll
                for (int f = 0; f < 8; f++)
                    mma_f16(s[f], qfh[dk], &kf[f >> 1][(f & 1) * 2]);
#pragma unroll
                for (int f = 0; f < 8; f++)
                    mma_f16(s[f], qfl[dk], &kf[f >> 1][(f & 1) * 2]);
            }

            // ---- masks ----
            const bool needc = (k0 + 63 > row0);
#pragma unroll
            for (int f = 0; f < 8; f++) {
                float2 pmv = *(float2*)(smem + AOFF_PM + (t % ASTAGES) * 256 + (f * 8 + c2) * 4);
                s[f][0] += pmv.x; s[f][1] += pmv.y;
                s[f][2] += pmv.x; s[f][3] += pmv.y;
                if (needc) {
                    int k = k0 + f * 8 + c2;
                    if (k     > row0) s[f][0] = -CUDART_INF_F;
                    if (k + 1 > row0) s[f][1] = -CUDART_INF_F;
                    if (k     > row1) s[f][2] = -CUDART_INF_F;
                    if (k + 1 > row1) s[f][3] = -CUDART_INF_F;
                }
            }

            // ---- online softmax (base 2) ----
            float mx0 = -CUDART_INF_F, mx1 = -CUDART_INF_F;
#pragma unroll
            for (int f = 0; f < 8; f++) {
                mx0 = fmaxf(mx0, fmaxf(s[f][0], s[f][1]));
                mx1 = fmaxf(mx1, fmaxf(s[f][2], s[f][3]));
            }
            mx0 = fmaxf(mx0, __shfl_xor_sync(0xffffffff, mx0, 1));
            mx0 = fmaxf(mx0, __shfl_xor_sync(0xffffffff, mx0, 2));
            mx1 = fmaxf(mx1, __shfl_xor_sync(0xffffffff, mx1, 1));
            mx1 = fmaxf(mx1, __shfl_xor_sync(0xffffffff, mx1, 2));
            const float mn0 = fmaxf(m0, mx0), mn1 = fmaxf(m1, mx1);
            const float al0 = exp2f(m0 - mn0), al1 = exp2f(m1 - mn1);
            m0 = mn0; m1 = mn1;

            uint32_t pah[4][4], pal[4][4];
            float rs0 = 0.f, rs1 = 0.f;
#pragma unroll
            for (int f = 0; f < 8; f++) {
                float p0 = exp2f(s[f][0] - mn0), p1 = exp2f(s[f][1] - mn0);
                float p2 = exp2f(s[f][2] - mn1), p3 = exp2f(s[f][3] - mn1);
                rs0 += p0 + p1; rs1 += p2 + p3;
                float q0, q1, q2, q3;
                const int ks = f >> 1, hi = (f & 1) * 2;
                pah[ks][hi]     = split_pack_hh(p0, p1, q0, q1);
                pah[ks][hi + 1] = split_pack_hh(p2, p3, q2, q3);
                pal[ks][hi]     = pack_h2(__float2half_rn(q0), __float2half_rn(q1));
                pal[ks][hi + 1] = pack_h2(__float2half_rn(q2), __float2half_rn(q3));
            }
            rs0 += __shfl_xor_sync(0xffffffff, rs0, 1);
            rs0 += __shfl_xor_sync(0xffffffff, rs0, 2);
            rs1 += __shfl_xor_sync(0xffffffff, rs1, 1);
            rs1 += __shfl_xor_sync(0xffffffff, rs1, 2);
            l0 = l0 * al0 + rs0;
            l1 = l1 * al1 + rs1;

#pragma unroll
            for (int nd = 0; nd < 8; nd++) {
                o[nd][0] *= al0; o[nd][1] *= al0;
                o[nd][2] *= al1; o[nd][3] *= al1;
            }

            // ---- O += (ph+pl) V, 2-pass fp16 ----
#pragma unroll
            for (int ks = 0; ks < 4; ks++) {
                uint32_t vf[4][4];
#pragma unroll
                for (int g = 0; g < 4; g++)
                    ldsm_x4_t(vf[g], st + AK_B + ((ks * 16 + v_r) * APITCH + g * 16 + v_c) * 2);
#pragma unroll
                for (int nd = 0; nd < 8; nd++)
                    mma_f16(o[nd], pah[ks], &vf[nd >> 1][(nd & 1) * 2]);
#pragma unroll
                for (int nd = 0; nd < 8; nd++)
                    mma_f16(o[nd], pal[ks], &vf[nd >> 1][(nd & 1) * 2]);
            }
        }
    }

    // ---- epilogue: O/l -> split bf16 into g_ah/g_al ----
    const float inv0 = (l0 > 0.f) ? (1.f / l0) : 0.f;
    const float inv1 = (l1 > 0.f) ? (1.f / l1) : 0.f;
    const size_t r0off = (size_t)(b * SEQ + row0) * DM + h * HD;
    const size_t r1off = (size_t)(b * SEQ + row1) * DM + h * HD;
#pragma unroll
    for (int nd = 0; nd < 8; nd++) {
        const int col = nd * 8 + c2;
        float v0 = o[nd][0] * inv0, v1 = o[nd][1] * inv0;
        float v2 = o[nd][2] * inv1, v3 = o[nd][3] * inv1;
        __nv_bfloat16 h0, ll0, h1, ll1, h2, ll2, h3, ll3;
        split2(v0, h0, ll0); split2(v1, h1, ll1);
        split2(v2, h2, ll2); split2(v3, h3, ll3);
        *(uint32_t*)&g_ah[r0off + col] = pack_bf2(h0, h1);
        *(uint32_t*)&g_ah[r1off + col] = pack_bf2(h2, h3);
        *(uint32_t*)&g_al[r0off + col] = pack_bf2(ll0, ll1);
        *(uint32_t*)&g_al[r1off + col] = pack_bf2(ll2, ll3);
    }
}

// ---- Launch ------------------------------------------------------------------------
#define QKV_SMEM (STAGES * 3 * TILE_B)   // 92160
#define OUT_SMEM (STAGES * 4 * TILE_B)   // 122880

extern "C" void kernel_launch(void* const* d_in, const int* in_sizes, int n_in,
                              void* d_out, int out_size)
{
    (void)in_sizes; (void)n_in; (void)out_size;
    const float*         x   = (const float*)d_in[0];
    const unsigned char* pad = (const unsigned char*)d_in[1];
    const float*         Wq  = (const float*)d_in[2];
    const float*         Wk  = (const float*)d_in[3];
    const float*         Wv  = (const float*)d_in[4];
    const float*         Wo  = (const float*)d_in[5];
    float*               out = (float*)d_out;

    cudaFuncSetAttribute(qkv_mma_kernel, cudaFuncAttributeMaxDynamicSharedMemorySize, QKV_SMEM);
    cudaFuncSetAttribute(out_mma_kernel, cudaFuncAttributeMaxDynamicSharedMemorySize, OUT_SMEM);
    cudaFuncSetAttribute(attn_kernel, cudaFuncAttributeMaxDynamicSharedMemorySize, ATTN_SMEM);

    conv_x_kernel<<<MROWS * DM / 4 / 256, 256>>>(x);
    conv_wt_kernel<<<dim3(DM / 32, DM / 32, 4), dim3(32, 8)>>>(Wq, Wk, Wv, Wo);

    qkv_mma_kernel<<<dim3(DM / BN, MROWS / BM, 3), 256, QKV_SMEM>>>();

    attn_kernel<<<dim3(SEQ / 128, BATCH * NH), 256, ATTN_SMEM>>>(pad);

    out_mma_kernel<<<dim3(DM / BN, MROWS / BM), 256, OUT_SMEM>>>(out);
}

// round 9
// speedup vs baseline: 6.5712x; 1.2879x over previous
#include <cuda_runtime.h>
#include <cuda_bf16.h>
#include <cuda_fp16.h>
#include <math_constants.h>
#include <cstdint>

// ---------------------------------------------------------------------------
// MHA Round 9: 2 CTAs/SM everywhere (launch_bounds 256,2), P single fp16 in
// PV, out projection 2-pass fp16 (A split-fp16, Wo single fp16).
// ---------------------------------------------------------------------------

#define BATCH 4
#define SEQ   2048
#define DM    1024
#define NH    16
#define HD    64
#define MROWS (BATCH * SEQ)
#define ATT_SCALE 0.125f
#define LOG2E 1.44269504088896340736f

#define BM 128
#define BN 128
#define BK 32
#define NCH (DM / BK)
#define STAGES 3
#define PITCH 40
#define TILE_B (128 * PITCH * 2)       // 10240
#define GEMM3_SMEM (STAGES * 3 * TILE_B)   // 92160 (A-hi, A-lo, B)

// attention smem
#define APITCH 72
#define AQ_B   (128 * APITCH * 2)      // 18432 per Q operand
#define AK_B   (64 * APITCH * 2)       // 9216 per K/V tile
#define ASTG_B (2 * AK_B)              // 18432 per stage (K, V)
#define ASTAGES 3
#define AOFF_Q  0
#define AOFF_ST (2 * AQ_B)                   // 36864
#define AOFF_PM (AOFF_ST + ASTAGES * ASTG_B) // 92160
#define ATTN_SMEM (AOFF_PM + 768)            // 92928

// ---- scratch ----------------------------------------------------------------
__device__ __align__(256) __half g_xh[MROWS * DM];
__device__ __align__(256) __half g_xl[MROWS * DM];
__device__ __align__(256) __half g_qh[MROWS * DM];
__device__ __align__(256) __half g_ql[MROWS * DM];
__device__ __align__(256) __half g_k [MROWS * DM];
__device__ __align__(256) __half g_v [MROWS * DM];
__device__ __align__(256) __half g_ah[MROWS * DM];
__device__ __align__(256) __half g_al[MROWS * DM];
__device__ __align__(256) __half g_wf[4][DM * DM];        // W^T fp16: q,k,v,o

// ---- helpers ------------------------------------------------------------------
__device__ __forceinline__ uint32_t smem_to_u32(const void* p) {
    uint32_t a;
    asm("{ .reg .u64 t; cvta.to.shared.u64 t, %1; cvt.u32.u64 %0, t; }"
        : "=r"(a) : "l"(p));
    return a;
}
__device__ __forceinline__ void mma_f16(float* d, const uint32_t* a, const uint32_t* b) {
    asm volatile(
        "mma.sync.aligned.m16n8k16.row.col.f32.f16.f16.f32 "
        "{%0,%1,%2,%3}, {%4,%5,%6,%7}, {%8,%9}, {%0,%1,%2,%3};\n"
        : "+f"(d[0]), "+f"(d[1]), "+f"(d[2]), "+f"(d[3])
        : "r"(a[0]), "r"(a[1]), "r"(a[2]), "r"(a[3]), "r"(b[0]), "r"(b[1]));
}
__device__ __forceinline__ void ldsm_x4(uint32_t* r, uint32_t addr) {
    asm volatile("ldmatrix.sync.aligned.m8n8.x4.shared.b16 {%0,%1,%2,%3}, [%4];"
        : "=r"(r[0]), "=r"(r[1]), "=r"(r[2]), "=r"(r[3]) : "r"(addr));
}
__device__ __forceinline__ void ldsm_x4_t(uint32_t* r, uint32_t addr) {
    asm volatile("ldmatrix.sync.aligned.m8n8.x4.trans.shared.b16 {%0,%1,%2,%3}, [%4];"
        : "=r"(r[0]), "=r"(r[1]), "=r"(r[2]), "=r"(r[3]) : "r"(addr));
}
__device__ __forceinline__ void cpasync16(uint32_t dst, const void* src) {
    asm volatile("cp.async.cg.shared.global [%0], [%1], 16;" :: "r"(dst), "l"(src));
}
__device__ __forceinline__ void split2h(float v, __half& h, __half& l) {
    h = __float2half_rn(v);
    l = __float2half_rn(v - __half2float(h));
}
__device__ __forceinline__ uint32_t pack_h2(__half a, __half b) {
    __half2 t = __halves2half2(a, b);
    return *(uint32_t*)&t;
}

// ---- GEMM body ------------------------------------------------------------------
// A split fp16 (2-pass), B single fp16.
// OMODE: 0 fp32 C; 1 split-fp16 (Ch,Cl) scaled; 2 single-fp16 (Ch) scaled.
template<int OMODE>
__device__ __forceinline__ void gemm_body(
    const __half* Ah_, const __half* Al_, const __half* B_,
    float* __restrict__ C, __half* __restrict__ Ch, __half* __restrict__ Cl,
    float scale)
{
    constexpr int STAGE_B = 3 * TILE_B;
    extern __shared__ char smem[];
    const uint32_t sb = smem_to_u32(smem);
    const int tid  = threadIdx.x;
    const int lane = tid & 31;
    const int wid  = tid >> 5;
    const int wm   = wid >> 2;
    const int wn   = wid & 3;
    const int bm = blockIdx.y, bn = blockIdx.x;

    const __half* gsrc[3] = {
        Ah_ + (size_t)bm * BM * DM,
        Al_ + (size_t)bm * BM * DM,
        B_  + (size_t)bn * BN * DM
    };

    float acc[4][4][4];
#pragma unroll
    for (int i = 0; i < 4; i++)
#pragma unroll
        for (int j = 0; j < 4; j++)
#pragma unroll
            for (int r = 0; r < 4; r++) acc[i][j][r] = 0.f;

    auto issue = [&](int c) {
        if (c < NCH) {
            const uint32_t sbase = sb + (c % STAGES) * STAGE_B;
            const size_t koff = (size_t)c * BK;
#pragma unroll
            for (int i = 0; i < 6; i++) {
                int q = tid + i * 256;
                int t = q >> 9, r = (q >> 2) & 127, c16 = q & 3;
                cpasync16(sbase + t * TILE_B + (r * PITCH + c16 * 8) * 2,
                          gsrc[t] + (size_t)r * DM + koff + c16 * 8);
            }
        }
        asm volatile("cp.async.commit_group;");
    };

    issue(0); issue(1);

    const int a_r = (lane & 7) + ((lane >> 3) & 1) * 8;
    const int a_c = (lane >> 4) * 8;
    const int b_r = (lane & 7) + ((lane >> 4) & 1) * 8;
    const int b_c = ((lane >> 3) & 1) * 8;

    for (int c = 0; c < NCH; c++) {
        asm volatile("cp.async.wait_group %0;" :: "n"(1));
        __syncthreads();
        issue(c + 2);

        const uint32_t st = sb + (c % STAGES) * STAGE_B;
        const uint32_t sAh = st, sAl = st + TILE_B, sB = st + 2 * TILE_B;

#pragma unroll
        for (int k16 = 0; k16 < 2; k16++) {
            const int kc = k16 * 16;
            uint32_t ah[4][4], al[4][4], bh[2][4];
#pragma unroll
            for (int mfi = 0; mfi < 4; mfi++)
                ldsm_x4(ah[mfi], sAh + ((wm * 64 + mfi * 16 + a_r) * PITCH + kc + a_c) * 2);
#pragma unroll
            for (int nfp = 0; nfp < 2; nfp++)
                ldsm_x4(bh[nfp], sB + ((wn * 32 + nfp * 16 + b_r) * PITCH + kc + b_c) * 2);
#pragma unroll
            for (int mfi = 0; mfi < 4; mfi++)
#pragma unroll
                for (int nf = 0; nf < 4; nf++)
                    mma_f16(acc[mfi][nf], ah[mfi], &bh[nf >> 1][(nf & 1) * 2]);
#pragma unroll
            for (int mfi = 0; mfi < 4; mfi++)
                ldsm_x4(al[mfi], sAl + ((wm * 64 + mfi * 16 + a_r) * PITCH + kc + a_c) * 2);
#pragma unroll
            for (int mfi = 0; mfi < 4; mfi++)
#pragma unroll
                for (int nf = 0; nf < 4; nf++)
                    mma_f16(acc[mfi][nf], al[mfi], &bh[nf >> 1][(nf & 1) * 2]);
        }
    }

#pragma unroll
    for (int mfi = 0; mfi < 4; mfi++)
#pragma unroll
        for (int nf = 0; nf < 4; nf++) {
            int row = bm * BM + wm * 64 + mfi * 16 + (lane >> 2);
            int col = bn * BN + wn * 32 + nf * 8 + (lane & 3) * 2;
            float v0 = acc[mfi][nf][0] * scale, v1 = acc[mfi][nf][1] * scale;
            float v2 = acc[mfi][nf][2] * scale, v3 = acc[mfi][nf][3] * scale;
            if (OMODE == 0) {
                *(float2*)&C[(size_t)row * DM + col]       = make_float2(v0, v1);
                *(float2*)&C[(size_t)(row + 8) * DM + col] = make_float2(v2, v3);
            } else if (OMODE == 1) {
                __half h0, l0, h1, l1, h2, l2, h3, l3;
                split2h(v0, h0, l0); split2h(v1, h1, l1);
                split2h(v2, h2, l2); split2h(v3, h3, l3);
                *(uint32_t*)&Ch[(size_t)row * DM + col]       = pack_h2(h0, h1);
                *(uint32_t*)&Ch[(size_t)(row + 8) * DM + col] = pack_h2(h2, h3);
                *(uint32_t*)&Cl[(size_t)row * DM + col]       = pack_h2(l0, l1);
                *(uint32_t*)&Cl[(size_t)(row + 8) * DM + col] = pack_h2(l2, l3);
            } else {
                *(uint32_t*)&Ch[(size_t)row * DM + col] =
                    pack_h2(__float2half_rn(v0), __float2half_rn(v1));
                *(uint32_t*)&Ch[(size_t)(row + 8) * DM + col] =
                    pack_h2(__float2half_rn(v2), __float2half_rn(v3));
            }
        }
}

__global__ __launch_bounds__(256, 2)
void qkv_mma_kernel()
{
    const int z = blockIdx.z;
    if (z == 0)
        gemm_body<1>(g_xh, g_xl, g_wf[0], nullptr, g_qh, g_ql, ATT_SCALE * LOG2E);
    else if (z == 1)
        gemm_body<2>(g_xh, g_xl, g_wf[1], nullptr, g_k, nullptr, 1.f);
    else
        gemm_body<2>(g_xh, g_xl, g_wf[2], nullptr, g_v, nullptr, 1.f);
}
__global__ __launch_bounds__(256, 2)
void out_mma_kernel(float* __restrict__ out)
{
    gemm_body<0>(g_ah, g_al, g_wf[3], out, nullptr, nullptr, 1.f);
}

// ---- conversions --------------------------------------------------------------
__global__ __launch_bounds__(256) void conv_x_kernel(const float* __restrict__ s) {
    int i = blockIdx.x * 256 + threadIdx.x;
    float4 v = ((const float4*)s)[i];
    __half h0,h1,h2,h3,l0,l1,l2,l3;
    split2h(v.x,h0,l0); split2h(v.y,h1,l1); split2h(v.z,h2,l2); split2h(v.w,h3,l3);
    ((uint32_t*)g_xh)[i*2+0] = pack_h2(h0,h1);
    ((uint32_t*)g_xh)[i*2+1] = pack_h2(h2,h3);
    ((uint32_t*)g_xl)[i*2+0] = pack_h2(l0,l1);
    ((uint32_t*)g_xl)[i*2+1] = pack_h2(l2,l3);
}
__global__ __launch_bounds__(256) void conv_wt_kernel(const float* __restrict__ W0,
                                                      const float* __restrict__ W1,
                                                      const float* __restrict__ W2,
                                                      const float* __restrict__ W3) {
    __shared__ float tile[32][33];
    const int z = blockIdx.z;
    const float* W = (z == 0) ? W0 : (z == 1) ? W1 : (z == 2) ? W2 : W3;
    const int n0 = blockIdx.x * 32, k0 = blockIdx.y * 32;
    const int tx = threadIdx.x, ty = threadIdx.y;
#pragma unroll
    for (int i = ty; i < 32; i += 8)
        tile[i][tx] = W[(size_t)(k0 + i) * DM + n0 + tx];
    __syncthreads();
#pragma unroll
    for (int i = ty; i < 32; i += 8)
        g_wf[z][(size_t)(n0 + i) * DM + k0 + tx] = __float2half_rn(tile[tx][i]);
}

// ---- Flash attention (fp16 operands, base-2 softmax, single-P PV) ----------------
__global__ __launch_bounds__(256, 2)
void attn_kernel(const unsigned char* __restrict__ pad)
{
    extern __shared__ char smem[];
    const uint32_t sb = smem_to_u32(smem);
    const int tid = threadIdx.x, lane = tid & 31, wq = tid >> 5;
    const int b = blockIdx.y >> 4, h = blockIdx.y & 15;
    const int bx = (gridDim.x - 1) - blockIdx.x;   // heavy blocks first
    const int qbase = bx * 128;
    const int ntiles = bx * 2 + 2;

    // Q (qh, ql) load — bundled into commit group 0
    {
        const __half* srcq[2] = {
            g_qh + (size_t)(b * SEQ + qbase) * DM + h * HD,
            g_ql + (size_t)(b * SEQ + qbase) * DM + h * HD };
#pragma unroll
        for (int i = 0; i < 8; i++) {
            int q = tid + i * 256;
            int op = q >> 10, row = (q >> 3) & 127, ch = q & 7;
            cpasync16(sb + AOFF_Q + op * AQ_B + (row * APITCH + ch * 8) * 2,
                      srcq[op] + (size_t)row * DM + ch * 8);
        }
    }

    auto issue = [&](int t) {
        if (t < ntiles) {
            const int k0 = t * 64;
            const uint32_t sbase = sb + AOFF_ST + (t % ASTAGES) * ASTG_B;
            const __half* gs[2] = {
                g_k + (size_t)(b * SEQ + k0) * DM + h * HD,
                g_v + (size_t)(b * SEQ + k0) * DM + h * HD };
#pragma unroll
            for (int i = 0; i < 4; i++) {
                int q = tid + i * 256;
                int tt = q >> 9, row = (q >> 3) & 63, ch = q & 7;
                cpasync16(sbase + tt * AK_B + (row * APITCH + ch * 8) * 2,
                          gs[tt] + (size_t)row * DM + ch * 8);
            }
        }
        asm volatile("cp.async.commit_group;");
    };
    auto pmload = [&](int t) {
        if (t < ntiles && tid < 64) {
            float v = pad[b * SEQ + t * 64 + tid] ? -CUDART_INF_F : 0.f;
            *(float*)(smem + AOFF_PM + (t % ASTAGES) * 256 + tid * 4) = v;
        }
    };

    pmload(0); issue(0);
    pmload(1); issue(1);

    const int r  = lane >> 2;
    const int c2 = (lane & 3) * 2;
    const int row0 = qbase + wq * 16 + r;
    const int row1 = row0 + 8;
    const int qmax = qbase + wq * 16 + 15;

    const int a_r = (lane & 7) + ((lane >> 3) & 1) * 8;
    const int a_c = (lane >> 4) * 8;
    const int b_r = (lane & 7) + ((lane >> 4) & 1) * 8;
    const int b_c = ((lane >> 3) & 1) * 8;
    const int v_r = (lane & 7) + ((lane >> 3) & 1) * 8;
    const int v_c = (lane >> 4) * 8;

    float m0 = -CUDART_INF_F, m1 = -CUDART_INF_F, l0 = 0.f, l1 = 0.f;
    float o[8][4];
#pragma unroll
    for (int i = 0; i < 8; i++)
#pragma unroll
        for (int j = 0; j < 4; j++) o[i][j] = 0.f;

    uint32_t qfh[4][4], qfl[4][4];

    for (int t = 0; t < ntiles; t++) {
        asm volatile("cp.async.wait_group %0;" :: "n"(1));
        __syncthreads();

        if (t == 0) {
#pragma unroll
            for (int dk = 0; dk < 4; dk++) {
                ldsm_x4(qfh[dk], sb + AOFF_Q +        ((wq * 16 + a_r) * APITCH + dk * 16 + a_c) * 2);
                ldsm_x4(qfl[dk], sb + AOFF_Q + AQ_B + ((wq * 16 + a_r) * APITCH + dk * 16 + a_c) * 2);
            }
        }
        pmload(t + 2);
        issue(t + 2);

        const int k0 = t * 64;
        if (k0 <= qmax) {
            const uint32_t st = sb + AOFF_ST + (t % ASTAGES) * ASTG_B;
            // ---- S = (qh+ql) K^T, 2-pass fp16 ----
            float s[8][4];
#pragma unroll
            for (int f = 0; f < 8; f++)
#pragma unroll
                for (int j = 0; j < 4; j++) s[f][j] = 0.f;

#pragma unroll
            for (int dk = 0; dk < 4; dk++) {
                uint32_t kf[4][4];
#pragma unroll
                for (int g = 0; g < 4; g++)
                    ldsm_x4(kf[g], st + ((g * 16 + b_r) * APITCH + dk * 16 + b_c) * 2);
#pragma unroll
                for (int f = 0; f < 8; f++)
                    mma_f16(s[f], qfh[dk], &kf[f >> 1][(f & 1) * 2]);
#pragma unroll
                for (int f = 0; f < 8; f++)
                    mma_f16(s[f], qfl[dk], &kf[f >> 1][(f & 1) * 2]);
            }

            // ---- masks ----
            const bool needc = (k0 + 63 > row0);
#pragma unroll
            for (int f = 0; f < 8; f++) {
                float2 pmv = *(float2*)(smem + AOFF_PM + (t % ASTAGES) * 256 + (f * 8 + c2) * 4);
                s[f][0] += pmv.x; s[f][1] += pmv.y;
                s[f][2] += pmv.x; s[f][3] += pmv.y;
                if (needc) {
                    int k = k0 + f * 8 + c2;
                    if (k     > row0) s[f][0] = -CUDART_INF_F;
                    if (k + 1 > row0) s[f][1] = -CUDART_INF_F;
                    if (k     > row1) s[f][2] = -CUDART_INF_F;
                    if (k + 1 > row1) s[f][3] = -CUDART_INF_F;
                }
            }

            // ---- online softmax (base 2) ----
            float mx0 = -CUDART_INF_F, mx1 = -CUDART_INF_F;
#pragma unroll
            for (int f = 0; f < 8; f++) {
                mx0 = fmaxf(mx0, fmaxf(s[f][0], s[f][1]));
                mx1 = fmaxf(mx1, fmaxf(s[f][2], s[f][3]));
            }
            mx0 = fmaxf(mx0, __shfl_xor_sync(0xffffffff, mx0, 1));
            mx0 = fmaxf(mx0, __shfl_xor_sync(0xffffffff, mx0, 2));
            mx1 = fmaxf(mx1, __shfl_xor_sync(0xffffffff, mx1, 1));
            mx1 = fmaxf(mx1, __shfl_xor_sync(0xffffffff, mx1, 2));
            const float mn0 = fmaxf(m0, mx0), mn1 = fmaxf(m1, mx1);
            const float al0 = exp2f(m0 - mn0), al1 = exp2f(m1 - mn1);
            m0 = mn0; m1 = mn1;

            uint32_t pah[4][4];
            float rs0 = 0.f, rs1 = 0.f;
#pragma unroll
            for (int f = 0; f < 8; f++) {
                float p0 = exp2f(s[f][0] - mn0), p1 = exp2f(s[f][1] - mn0);
                float p2 = exp2f(s[f][2] - mn1), p3 = exp2f(s[f][3] - mn1);
                rs0 += p0 + p1; rs1 += p2 + p3;
                const int ks = f >> 1, hi = (f & 1) * 2;
                pah[ks][hi]     = pack_h2(__float2half_rn(p0), __float2half_rn(p1));
                pah[ks][hi + 1] = pack_h2(__float2half_rn(p2), __float2half_rn(p3));
            }
            rs0 += __shfl_xor_sync(0xffffffff, rs0, 1);
            rs0 += __shfl_xor_sync(0xffffffff, rs0, 2);
            rs1 += __shfl_xor_sync(0xffffffff, rs1, 1);
            rs1 += __shfl_xor_sync(0xffffffff, rs1, 2);
            l0 = l0 * al0 + rs0;
            l1 = l1 * al1 + rs1;

#pragma unroll
            for (int nd = 0; nd < 8; nd++) {
                o[nd][0] *= al0; o[nd][1] *= al0;
                o[nd][2] *= al1; o[nd][3] *= al1;
            }

            // ---- O += P V, single-pass fp16 ----
#pragma unroll
            for (int ks = 0; ks < 4; ks++) {
                uint32_t vf[4][4];
#pragma unroll
                for (int g = 0; g < 4; g++)
                    ldsm_x4_t(vf[g], st + AK_B + ((ks * 16 + v_r) * APITCH + g * 16 + v_c) * 2);
#pragma unroll
                for (int nd = 0; nd < 8; nd++)
                    mma_f16(o[nd], pah[ks], &vf[nd >> 1][(nd & 1) * 2]);
            }
        }
    }

    // ---- epilogue: O/l -> split fp16 into g_ah/g_al ----
    const float inv0 = (l0 > 0.f) ? (1.f / l0) : 0.f;
    const float inv1 = (l1 > 0.f) ? (1.f / l1) : 0.f;
    const size_t r0off = (size_t)(b * SEQ + row0) * DM + h * HD;
    const size_t r1off = (size_t)(b * SEQ + row1) * DM + h * HD;
#pragma unroll
    for (int nd = 0; nd < 8; nd++) {
        const int col = nd * 8 + c2;
        float v0 = o[nd][0] * inv0, v1 = o[nd][1] * inv0;
        float v2 = o[nd][2] * inv1, v3 = o[nd][3] * inv1;
        __half h0, ll0, h1, ll1, h2, ll2, h3, ll3;
        split2h(v0, h0, ll0); split2h(v1, h1, ll1);
        split2h(v2, h2, ll2); split2h(v3, h3, ll3);
        *(uint32_t*)&g_ah[r0off + col] = pack_h2(h0, h1);
        *(uint32_t*)&g_ah[r1off + col] = pack_h2(h2, h3);
        *(uint32_t*)&g_al[r0off + col] = pack_h2(ll0, ll1);
        *(uint32_t*)&g_al[r1off + col] = pack_h2(ll2, ll3);
    }
}

// ---- Launch ------------------------------------------------------------------------
extern "C" void kernel_launch(void* const* d_in, const int* in_sizes, int n_in,
                              void* d_out, int out_size)
{
    (void)in_sizes; (void)n_in; (void)out_size;
    const float*         x   = (const float*)d_in[0];
    const unsigned char* pad = (const unsigned char*)d_in[1];
    const float*         Wq  = (const float*)d_in[2];
    const float*         Wk  = (const float*)d_in[3];
    const float*         Wv  = (const float*)d_in[4];
    const float*         Wo  = (const float*)d_in[5];
    float*               out = (float*)d_out;

    cudaFuncSetAttribute(qkv_mma_kernel, cudaFuncAttributeMaxDynamicSharedMemorySize, GEMM3_SMEM);
    cudaFuncSetAttribute(out_mma_kernel, cudaFuncAttributeMaxDynamicSharedMemorySize, GEMM3_SMEM);
    cudaFuncSetAttribute(attn_kernel, cudaFuncAttributeMaxDynamicSharedMemorySize, ATTN_SMEM);

    conv_x_kernel<<<MROWS * DM / 4 / 256, 256>>>(x);
    conv_wt_kernel<<<dim3(DM / 32, DM / 32, 4), dim3(32, 8)>>>(Wq, Wk, Wv, Wo);

    qkv_mma_kernel<<<dim3(DM / BN, MROWS / BM, 3), 256, GEMM3_SMEM>>>();

    attn_kernel<<<dim3(SEQ / 128, BATCH * NH), 256, ATTN_SMEM>>>(pad);

    out_mma_kernel<<<dim3(DM / BN, MROWS / BM), 256, GEMM3_SMEM>>>(out);
}

// round 10
// speedup vs baseline: 7.8281x; 1.1913x over previous
#include <cuda_runtime.h>
#include <cuda_bf16.h>
#include <cuda_fp16.h>
#include <math_constants.h>
#include <cstdint>

// ---------------------------------------------------------------------------
// MHA Round 10: spend precision budget for speed.
//  qkv : (xh+xl) @ W fp16 2-pass -> Q,K,V single fp16 (Q pre-scaled w/ log2e)
//  attn: QK single-pass fp16, PV single-pass fp16, base-2 softmax -> A fp16
//  out : A @ Wo fp16 single-A-pass
// Error model (calibrated): ~6.5e-4 predicted vs 1e-3 gate.
// ---------------------------------------------------------------------------

#define BATCH 4
#define SEQ   2048
#define DM    1024
#define NH    16
#define HD    64
#define MROWS (BATCH * SEQ)
#define ATT_SCALE 0.125f
#define LOG2E 1.44269504088896340736f

#define BM 128
#define BN 128
#define BK 32
#define NCH (DM / BK)
#define STAGES 3
#define PITCH 40
#define TILE_B (128 * PITCH * 2)           // 10240
#define QKV_SMEM (STAGES * 3 * TILE_B)     // 92160 (xh, xl, W)
#define OUT_SMEM (STAGES * 2 * TILE_B)     // 61440 (A, Wo)

// attention smem
#define APITCH 72
#define AQ_B   (128 * APITCH * 2)          // 18432 (single Q)
#define AK_B   (64 * APITCH * 2)           // 9216 per K/V tile
#define ASTG_B (2 * AK_B)                  // 18432 per stage (K, V)
#define ASTAGES 3
#define AOFF_Q  0
#define AOFF_ST AQ_B                          // 18432
#define AOFF_PM (AOFF_ST + ASTAGES * ASTG_B)  // 73728
#define ATTN_SMEM (AOFF_PM + 768)             // 74496

// ---- scratch ----------------------------------------------------------------
__device__ __align__(256) __half g_xh[MROWS * DM];
__device__ __align__(256) __half g_xl[MROWS * DM];
__device__ __align__(256) __half g_q [MROWS * DM];
__device__ __align__(256) __half g_k [MROWS * DM];
__device__ __align__(256) __half g_v [MROWS * DM];
__device__ __align__(256) __half g_a [MROWS * DM];
__device__ __align__(256) __half g_wf[4][DM * DM];        // W^T fp16: q,k,v,o

// ---- helpers ------------------------------------------------------------------
__device__ __forceinline__ uint32_t smem_to_u32(const void* p) {
    uint32_t a;
    asm("{ .reg .u64 t; cvta.to.shared.u64 t, %1; cvt.u32.u64 %0, t; }"
        : "=r"(a) : "l"(p));
    return a;
}
__device__ __forceinline__ void mma_f16(float* d, const uint32_t* a, const uint32_t* b) {
    asm volatile(
        "mma.sync.aligned.m16n8k16.row.col.f32.f16.f16.f32 "
        "{%0,%1,%2,%3}, {%4,%5,%6,%7}, {%8,%9}, {%0,%1,%2,%3};\n"
        : "+f"(d[0]), "+f"(d[1]), "+f"(d[2]), "+f"(d[3])
        : "r"(a[0]), "r"(a[1]), "r"(a[2]), "r"(a[3]), "r"(b[0]), "r"(b[1]));
}
__device__ __forceinline__ void ldsm_x4(uint32_t* r, uint32_t addr) {
    asm volatile("ldmatrix.sync.aligned.m8n8.x4.shared.b16 {%0,%1,%2,%3}, [%4];"
        : "=r"(r[0]), "=r"(r[1]), "=r"(r[2]), "=r"(r[3]) : "r"(addr));
}
__device__ __forceinline__ void ldsm_x4_t(uint32_t* r, uint32_t addr) {
    asm volatile("ldmatrix.sync.aligned.m8n8.x4.trans.shared.b16 {%0,%1,%2,%3}, [%4];"
        : "=r"(r[0]), "=r"(r[1]), "=r"(r[2]), "=r"(r[3]) : "r"(addr));
}
__device__ __forceinline__ void cpasync16(uint32_t dst, const void* src) {
    asm volatile("cp.async.cg.shared.global [%0], [%1], 16;" :: "r"(dst), "l"(src));
}
__device__ __forceinline__ void split2h(float v, __half& h, __half& l) {
    h = __float2half_rn(v);
    l = __float2half_rn(v - __half2float(h));
}
__device__ __forceinline__ uint32_t pack_h2(__half a, __half b) {
    __half2 t = __halves2half2(a, b);
    return *(uint32_t*)&t;
}

// ---- GEMM body ------------------------------------------------------------------
// APASS: 1 (A single) or 2 (A split hi/lo). B always single fp16.
// OMODE: 0 fp32 C; 2 single-fp16 (Ch) scaled.
template<int APASS, int OMODE>
__device__ __forceinline__ void gemm_body(
    const __half* Ah_, const __half* Al_, const __half* B_,
    float* __restrict__ C, __half* __restrict__ Ch, float scale)
{
    constexpr int NT = APASS + 1;
    constexpr int STAGE_B = NT * TILE_B;
    extern __shared__ char smem[];
    const uint32_t sb = smem_to_u32(smem);
    const int tid  = threadIdx.x;
    const int lane = tid & 31;
    const int wid  = tid >> 5;
    const int wm   = wid >> 2;
    const int wn   = wid & 3;
    const int bm = blockIdx.y, bn = blockIdx.x;

    const __half* gsrc[NT];
    gsrc[0] = Ah_ + (size_t)bm * BM * DM;
    if (APASS == 2) gsrc[1] = Al_ + (size_t)bm * BM * DM;
    gsrc[NT - 1] = B_ + (size_t)bn * BN * DM;

    float acc[4][4][4];
#pragma unroll
    for (int i = 0; i < 4; i++)
#pragma unroll
        for (int j = 0; j < 4; j++)
#pragma unroll
            for (int r = 0; r < 4; r++) acc[i][j][r] = 0.f;

    auto issue = [&](int c) {
        if (c < NCH) {
            const uint32_t sbase = sb + (c % STAGES) * STAGE_B;
            const size_t koff = (size_t)c * BK;
#pragma unroll
            for (int i = 0; i < 2 * NT; i++) {
                int q = tid + i * 256;
                int t = q >> 9, r = (q >> 2) & 127, c16 = q & 3;
                cpasync16(sbase + t * TILE_B + (r * PITCH + c16 * 8) * 2,
                          gsrc[t] + (size_t)r * DM + koff + c16 * 8);
            }
        }
        asm volatile("cp.async.commit_group;");
    };

    issue(0); issue(1);

    const int a_r = (lane & 7) + ((lane >> 3) & 1) * 8;
    const int a_c = (lane >> 4) * 8;
    const int b_r = (lane & 7) + ((lane >> 4) & 1) * 8;
    const int b_c = ((lane >> 3) & 1) * 8;

    for (int c = 0; c < NCH; c++) {
        asm volatile("cp.async.wait_group %0;" :: "n"(1));
        __syncthreads();
        issue(c + 2);

        const uint32_t st = sb + (c % STAGES) * STAGE_B;
        const uint32_t sAh = st;
        const uint32_t sAl = st + TILE_B;                // valid iff APASS==2
        const uint32_t sB  = st + (NT - 1) * TILE_B;

#pragma unroll
        for (int k16 = 0; k16 < 2; k16++) {
            const int kc = k16 * 16;
            uint32_t ah[4][4], al[4][4], bh[2][4];
#pragma unroll
            for (int mfi = 0; mfi < 4; mfi++)
                ldsm_x4(ah[mfi], sAh + ((wm * 64 + mfi * 16 + a_r) * PITCH + kc + a_c) * 2);
#pragma unroll
            for (int nfp = 0; nfp < 2; nfp++)
                ldsm_x4(bh[nfp], sB + ((wn * 32 + nfp * 16 + b_r) * PITCH + kc + b_c) * 2);
#pragma unroll
            for (int mfi = 0; mfi < 4; mfi++)
#pragma unroll
                for (int nf = 0; nf < 4; nf++)
                    mma_f16(acc[mfi][nf], ah[mfi], &bh[nf >> 1][(nf & 1) * 2]);
            if (APASS == 2) {
#pragma unroll
                for (int mfi = 0; mfi < 4; mfi++)
                    ldsm_x4(al[mfi], sAl + ((wm * 64 + mfi * 16 + a_r) * PITCH + kc + a_c) * 2);
#pragma unroll
                for (int mfi = 0; mfi < 4; mfi++)
#pragma unroll
                    for (int nf = 0; nf < 4; nf++)
                        mma_f16(acc[mfi][nf], al[mfi], &bh[nf >> 1][(nf & 1) * 2]);
            }
        }
    }

#pragma unroll
    for (int mfi = 0; mfi < 4; mfi++)
#pragma unroll
        for (int nf = 0; nf < 4; nf++) {
            int row = bm * BM + wm * 64 + mfi * 16 + (lane >> 2);
            int col = bn * BN + wn * 32 + nf * 8 + (lane & 3) * 2;
            float v0 = acc[mfi][nf][0] * scale, v1 = acc[mfi][nf][1] * scale;
            float v2 = acc[mfi][nf][2] * scale, v3 = acc[mfi][nf][3] * scale;
            if (OMODE == 0) {
                *(float2*)&C[(size_t)row * DM + col]       = make_float2(v0, v1);
                *(float2*)&C[(size_t)(row + 8) * DM + col] = make_float2(v2, v3);
            } else {
                *(uint32_t*)&Ch[(size_t)row * DM + col] =
                    pack_h2(__float2half_rn(v0), __float2half_rn(v1));
                *(uint32_t*)&Ch[(size_t)(row + 8) * DM + col] =
                    pack_h2(__float2half_rn(v2), __float2half_rn(v3));
            }
        }
}

__global__ __launch_bounds__(256, 2)
void qkv_mma_kernel()
{
    const int z = blockIdx.z;
    if (z == 0)
        gemm_body<2, 2>(g_xh, g_xl, g_wf[0], nullptr, g_q, ATT_SCALE * LOG2E);
    else if (z == 1)
        gemm_body<2, 2>(g_xh, g_xl, g_wf[1], nullptr, g_k, 1.f);
    else
        gemm_body<2, 2>(g_xh, g_xl, g_wf[2], nullptr, g_v, 1.f);
}
__global__ __launch_bounds__(256, 2)
void out_mma_kernel(float* __restrict__ out)
{
    gemm_body<1, 0>(g_a, nullptr, g_wf[3], out, nullptr, 1.f);
}

// ---- conversions --------------------------------------------------------------
__global__ __launch_bounds__(256) void conv_x_kernel(const float* __restrict__ s) {
    int i = blockIdx.x * 256 + threadIdx.x;
    float4 v = ((const float4*)s)[i];
    __half h0,h1,h2,h3,l0,l1,l2,l3;
    split2h(v.x,h0,l0); split2h(v.y,h1,l1); split2h(v.z,h2,l2); split2h(v.w,h3,l3);
    ((uint32_t*)g_xh)[i*2+0] = pack_h2(h0,h1);
    ((uint32_t*)g_xh)[i*2+1] = pack_h2(h2,h3);
    ((uint32_t*)g_xl)[i*2+0] = pack_h2(l0,l1);
    ((uint32_t*)g_xl)[i*2+1] = pack_h2(l2,l3);
}
__global__ __launch_bounds__(256) void conv_wt_kernel(const float* __restrict__ W0,
                                                      const float* __restrict__ W1,
                                                      const float* __restrict__ W2,
                                                      const float* __restrict__ W3) {
    __shared__ float tile[32][33];
    const int z = blockIdx.z;
    const float* W = (z == 0) ? W0 : (z == 1) ? W1 : (z == 2) ? W2 : W3;
    const int n0 = blockIdx.x * 32, k0 = blockIdx.y * 32;
    const int tx = threadIdx.x, ty = threadIdx.y;
#pragma unroll
    for (int i = ty; i < 32; i += 8)
        tile[i][tx] = W[(size_t)(k0 + i) * DM + n0 + tx];
    __syncthreads();
#pragma unroll
    for (int i = ty; i < 32; i += 8)
        g_wf[z][(size_t)(n0 + i) * DM + k0 + tx] = __float2half_rn(tile[tx][i]);
}

// ---- Flash attention (single-pass QK and PV, base-2 softmax) ---------------------
__global__ __launch_bounds__(256, 2)
void attn_kernel(const unsigned char* __restrict__ pad)
{
    extern __shared__ char smem[];
    const uint32_t sb = smem_to_u32(smem);
    const int tid = threadIdx.x, lane = tid & 31, wq = tid >> 5;
    const int b = blockIdx.y >> 4, h = blockIdx.y & 15;
    const int bx = (gridDim.x - 1) - blockIdx.x;   // heavy blocks first
    const int qbase = bx * 128;
    const int ntiles = bx * 2 + 2;

    // Q load (single operand) — bundled into commit group 0
    {
        const __half* srcq = g_q + (size_t)(b * SEQ + qbase) * DM + h * HD;
#pragma unroll
        for (int i = 0; i < 4; i++) {
            int q = tid + i * 256;
            int row = q >> 3, ch = q & 7;
            cpasync16(sb + AOFF_Q + (row * APITCH + ch * 8) * 2,
                      srcq + (size_t)row * DM + ch * 8);
        }
    }

    auto issue = [&](int t) {
        if (t < ntiles) {
            const int k0 = t * 64;
            const uint32_t sbase = sb + AOFF_ST + (t % ASTAGES) * ASTG_B;
            const __half* gs[2] = {
                g_k + (size_t)(b * SEQ + k0) * DM + h * HD,
                g_v + (size_t)(b * SEQ + k0) * DM + h * HD };
#pragma unroll
            for (int i = 0; i < 4; i++) {
                int q = tid + i * 256;
                int tt = q >> 9, row = (q >> 3) & 63, ch = q & 7;
                cpasync16(sbase + tt * AK_B + (row * APITCH + ch * 8) * 2,
                          gs[tt] + (size_t)row * DM + ch * 8);
            }
        }
        asm volatile("cp.async.commit_group;");
    };
    auto pmload = [&](int t) {
        if (t < ntiles && tid < 64) {
            float v = pad[b * SEQ + t * 64 + tid] ? -CUDART_INF_F : 0.f;
            *(float*)(smem + AOFF_PM + (t % ASTAGES) * 256 + tid * 4) = v;
        }
    };

    pmload(0); issue(0);
    pmload(1); issue(1);

    const int r  = lane >> 2;
    const int c2 = (lane & 3) * 2;
    const int row0 = qbase + wq * 16 + r;
    const int row1 = row0 + 8;
    const int qmax = qbase + wq * 16 + 15;

    const int a_r = (lane & 7) + ((lane >> 3) & 1) * 8;
    const int a_c = (lane >> 4) * 8;
    const int b_r = (lane & 7) + ((lane >> 4) & 1) * 8;
    const int b_c = ((lane >> 3) & 1) * 8;
    const int v_r = (lane & 7) + ((lane >> 3) & 1) * 8;
    const int v_c = (lane >> 4) * 8;

    float m0 = -CUDART_INF_F, m1 = -CUDART_INF_F, l0 = 0.f, l1 = 0.f;
    float o[8][4];
#pragma unroll
    for (int i = 0; i < 8; i++)
#pragma unroll
        for (int j = 0; j < 4; j++) o[i][j] = 0.f;

    uint32_t qf[4][4];

    for (int t = 0; t < ntiles; t++) {
        asm volatile("cp.async.wait_group %0;" :: "n"(1));
        __syncthreads();

        if (t == 0) {
#pragma unroll
            for (int dk = 0; dk < 4; dk++)
                ldsm_x4(qf[dk], sb + AOFF_Q + ((wq * 16 + a_r) * APITCH + dk * 16 + a_c) * 2);
        }
        pmload(t + 2);
        issue(t + 2);

        const int k0 = t * 64;
        if (k0 <= qmax) {
            const uint32_t st = sb + AOFF_ST + (t % ASTAGES) * ASTG_B;
            // ---- S = Q K^T, single-pass fp16 ----
            float s[8][4];
#pragma unroll
            for (int f = 0; f < 8; f++)
#pragma unroll
                for (int j = 0; j < 4; j++) s[f][j] = 0.f;

#pragma unroll
            for (int dk = 0; dk < 4; dk++) {
                uint32_t kf[4][4];
#pragma unroll
                for (int g = 0; g < 4; g++)
                    ldsm_x4(kf[g], st + ((g * 16 + b_r) * APITCH + dk * 16 + b_c) * 2);
#pragma unroll
                for (int f = 0; f < 8; f++)
                    mma_f16(s[f], qf[dk], &kf[f >> 1][(f & 1) * 2]);
            }

            // ---- masks ----
            const bool needc = (k0 + 63 > row0);
#pragma unroll
            for (int f = 0; f < 8; f++) {
                float2 pmv = *(float2*)(smem + AOFF_PM + (t % ASTAGES) * 256 + (f * 8 + c2) * 4);
                s[f][0] += pmv.x; s[f][1] += pmv.y;
                s[f][2] += pmv.x; s[f][3] += pmv.y;
                if (needc) {
                    int k = k0 + f * 8 + c2;
                    if (k     > row0) s[f][0] = -CUDART_INF_F;
                    if (k + 1 > row0) s[f][1] = -CUDART_INF_F;
                    if (k     > row1) s[f][2] = -CUDART_INF_F;
                    if (k + 1 > row1) s[f][3] = -CUDART_INF_F;
                }
            }

            // ---- online softmax (base 2) ----
            float mx0 = -CUDART_INF_F, mx1 = -CUDART_INF_F;
#pragma unroll
            for (int f = 0; f < 8; f++) {
                mx0 = fmaxf(mx0, fmaxf(s[f][0], s[f][1]));
                mx1 = fmaxf(mx1, fmaxf(s[f][2], s[f][3]));
            }
            mx0 = fmaxf(mx0, __shfl_xor_sync(0xffffffff, mx0, 1));
            mx0 = fmaxf(mx0, __shfl_xor_sync(0xffffffff, mx0, 2));
            mx1 = fmaxf(mx1, __shfl_xor_sync(0xffffffff, mx1, 1));
            mx1 = fmaxf(mx1, __shfl_xor_sync(0xffffffff, mx1, 2));
            const float mn0 = fmaxf(m0, mx0), mn1 = fmaxf(m1, mx1);
            const float al0 = exp2f(m0 - mn0), al1 = exp2f(m1 - mn1);
            m0 = mn0; m1 = mn1;

            uint32_t pah[4][4];
            float rs0 = 0.f, rs1 = 0.f;
#pragma unroll
            for (int f = 0; f < 8; f++) {
                float p0 = exp2f(s[f][0] - mn0), p1 = exp2f(s[f][1] - mn0);
                float p2 = exp2f(s[f][2] - mn1), p3 = exp2f(s[f][3] - mn1);
                rs0 += p0 + p1; rs1 += p2 + p3;
                const int ks = f >> 1, hi = (f & 1) * 2;
                pah[ks][hi]     = pack_h2(__float2half_rn(p0), __float2half_rn(p1));
                pah[ks][hi + 1] = pack_h2(__float2half_rn(p2), __float2half_rn(p3));
            }
            rs0 += __shfl_xor_sync(0xffffffff, rs0, 1);
            rs0 += __shfl_xor_sync(0xffffffff, rs0, 2);
            rs1 += __shfl_xor_sync(0xffffffff, rs1, 1);
            rs1 += __shfl_xor_sync(0xffffffff, rs1, 2);
            l0 = l0 * al0 + rs0;
            l1 = l1 * al1 + rs1;

#pragma unroll
            for (int nd = 0; nd < 8; nd++) {
                o[nd][0] *= al0; o[nd][1] *= al0;
                o[nd][2] *= al1; o[nd][3] *= al1;
            }

            // ---- O += P V, single-pass fp16 ----
#pragma unroll
            for (int ks = 0; ks < 4; ks++) {
                uint32_t vf[4][4];
#pragma unroll
                for (int g = 0; g < 4; g++)
                    ldsm_x4_t(vf[g], st + AK_B + ((ks * 16 + v_r) * APITCH + g * 16 + v_c) * 2);
#pragma unroll
                for (int nd = 0; nd < 8; nd++)
                    mma_f16(o[nd], pah[ks], &vf[nd >> 1][(nd & 1) * 2]);
            }
        }
    }

    // ---- epilogue: O/l -> single fp16 into g_a ----
    const float inv0 = (l0 > 0.f) ? (1.f / l0) : 0.f;
    const float inv1 = (l1 > 0.f) ? (1.f / l1) : 0.f;
    const size_t r0off = (size_t)(b * SEQ + row0) * DM + h * HD;
    const size_t r1off = (size_t)(b * SEQ + row1) * DM + h * HD;
#pragma unroll
    for (int nd = 0; nd < 8; nd++) {
        const int col = nd * 8 + c2;
        *(uint32_t*)&g_a[r0off + col] =
            pack_h2(__float2half_rn(o[nd][0] * inv0), __float2half_rn(o[nd][1] * inv0));
        *(uint32_t*)&g_a[r1off + col] =
            pack_h2(__float2half_rn(o[nd][2] * inv1), __float2half_rn(o[nd][3] * inv1));
    }
}

// ---- Launch ------------------------------------------------------------------------
extern "C" void kernel_launch(void* const* d_in, const int* in_sizes, int n_in,
                              void* d_out, int out_size)
{
    (void)in_sizes; (void)n_in; (void)out_size;
    const float*         x   = (const float*)d_in[0];
    const unsigned char* pad = (const unsigned char*)d_in[1];
    const float*         Wq  = (const float*)d_in[2];
    const float*         Wk  = (const float*)d_in[3];
    const float*         Wv  = (const float*)d_in[4];
    const float*         Wo  = (const float*)d_in[5];
    float*               out = (float*)d_out;

    cudaFuncSetAttribute(qkv_mma_kernel, cudaFuncAttributeMaxDynamicSharedMemorySize, QKV_SMEM);
    cudaFuncSetAttribute(out_mma_kernel, cudaFuncAttributeMaxDynamicSharedMemorySize, OUT_SMEM);
    cudaFuncSetAttribute(attn_kernel, cudaFuncAttributeMaxDynamicSharedMemorySize, ATTN_SMEM);

    conv_x_kernel<<<MROWS * DM / 4 / 256, 256>>>(x);
    conv_wt_kernel<<<dim3(DM / 32, DM / 32, 4), dim3(32, 8)>>>(Wq, Wk, Wv, Wo);

    qkv_mma_kernel<<<dim3(DM / BN, MROWS / BM, 3), 256, QKV_SMEM>>>();

    attn_kernel<<<dim3(SEQ / 128, BATCH * NH), 256, ATTN_SMEM>>>(pad);

    out_mma_kernel<<<dim3(DM / BN, MROWS / BM), 256, OUT_SMEM>>>(out);
}

// round 11
// speedup vs baseline: 10.2893x; 1.3144x over previous
#include <cuda_runtime.h>
#include <cuda_bf16.h>
#include <cuda_fp16.h>
#include <math_constants.h>
#include <cstdint>

// ---------------------------------------------------------------------------
// MHA Round 11: all projections single-pass fp16 (x single fp16), 4-stage
// GEMM pipelines. Attention unchanged from R10 (single-pass QK/PV, base-2
// softmax). Calibrated error model: ~7.1e-4 predicted vs 1e-3 gate.
// ---------------------------------------------------------------------------

#define BATCH 4
#define SEQ   2048
#define DM    1024
#define NH    16
#define HD    64
#define MROWS (BATCH * SEQ)
#define ATT_SCALE 0.125f
#define LOG2E 1.44269504088896340736f

#define BM 128
#define BN 128
#define BK 32
#define NCH (DM / BK)
#define GSTAGES 4
#define PITCH 40
#define TILE_B (128 * PITCH * 2)            // 10240
#define GEMM_SMEM (GSTAGES * 2 * TILE_B)    // 81920 (A, B per stage)

// attention smem
#define APITCH 72
#define AQ_B   (128 * APITCH * 2)           // 18432 (single Q)
#define AK_B   (64 * APITCH * 2)            // 9216 per K/V tile
#define ASTG_B (2 * AK_B)                   // 18432 per stage (K, V)
#define ASTAGES 3
#define AOFF_Q  0
#define AOFF_ST AQ_B                          // 18432
#define AOFF_PM (AOFF_ST + ASTAGES * ASTG_B)  // 73728
#define ATTN_SMEM (AOFF_PM + 768)             // 74496

// ---- scratch ----------------------------------------------------------------
__device__ __align__(256) __half g_x [MROWS * DM];
__device__ __align__(256) __half g_q [MROWS * DM];
__device__ __align__(256) __half g_k [MROWS * DM];
__device__ __align__(256) __half g_v [MROWS * DM];
__device__ __align__(256) __half g_a [MROWS * DM];
__device__ __align__(256) __half g_wf[4][DM * DM];        // W^T fp16: q,k,v,o

// ---- helpers ------------------------------------------------------------------
__device__ __forceinline__ uint32_t smem_to_u32(const void* p) {
    uint32_t a;
    asm("{ .reg .u64 t; cvta.to.shared.u64 t, %1; cvt.u32.u64 %0, t; }"
        : "=r"(a) : "l"(p));
    return a;
}
__device__ __forceinline__ void mma_f16(float* d, const uint32_t* a, const uint32_t* b) {
    asm volatile(
        "mma.sync.aligned.m16n8k16.row.col.f32.f16.f16.f32 "
        "{%0,%1,%2,%3}, {%4,%5,%6,%7}, {%8,%9}, {%0,%1,%2,%3};\n"
        : "+f"(d[0]), "+f"(d[1]), "+f"(d[2]), "+f"(d[3])
        : "r"(a[0]), "r"(a[1]), "r"(a[2]), "r"(a[3]), "r"(b[0]), "r"(b[1]));
}
__device__ __forceinline__ void ldsm_x4(uint32_t* r, uint32_t addr) {
    asm volatile("ldmatrix.sync.aligned.m8n8.x4.shared.b16 {%0,%1,%2,%3}, [%4];"
        : "=r"(r[0]), "=r"(r[1]), "=r"(r[2]), "=r"(r[3]) : "r"(addr));
}
__device__ __forceinline__ void ldsm_x4_t(uint32_t* r, uint32_t addr) {
    asm volatile("ldmatrix.sync.aligned.m8n8.x4.trans.shared.b16 {%0,%1,%2,%3}, [%4];"
        : "=r"(r[0]), "=r"(r[1]), "=r"(r[2]), "=r"(r[3]) : "r"(addr));
}
__device__ __forceinline__ void cpasync16(uint32_t dst, const void* src) {
    asm volatile("cp.async.cg.shared.global [%0], [%1], 16;" :: "r"(dst), "l"(src));
}
__device__ __forceinline__ uint32_t pack_h2(__half a, __half b) {
    __half2 t = __halves2half2(a, b);
    return *(uint32_t*)&t;
}

// ---- GEMM body: C[8192,1024] = A @ B^T, single-pass fp16, 4-stage pipeline ------
// OMODE: 0 fp32 C; 2 single-fp16 (Ch) scaled.
template<int OMODE>
__device__ __forceinline__ void gemm_body(
    const __half* A_, const __half* B_,
    float* __restrict__ C, __half* __restrict__ Ch, float scale)
{
    constexpr int STAGE_B = 2 * TILE_B;
    extern __shared__ char smem[];
    const uint32_t sb = smem_to_u32(smem);
    const int tid  = threadIdx.x;
    const int lane = tid & 31;
    const int wid  = tid >> 5;
    const int wm   = wid >> 2;
    const int wn   = wid & 3;
    const int bm = blockIdx.y, bn = blockIdx.x;

    const __half* gsrc[2] = {
        A_ + (size_t)bm * BM * DM,
        B_ + (size_t)bn * BN * DM
    };

    float acc[4][4][4];
#pragma unroll
    for (int i = 0; i < 4; i++)
#pragma unroll
        for (int j = 0; j < 4; j++)
#pragma unroll
            for (int r = 0; r < 4; r++) acc[i][j][r] = 0.f;

    auto issue = [&](int c) {
        if (c < NCH) {
            const uint32_t sbase = sb + (c % GSTAGES) * STAGE_B;
            const size_t koff = (size_t)c * BK;
#pragma unroll
            for (int i = 0; i < 4; i++) {
                int q = tid + i * 256;
                int t = q >> 9, r = (q >> 2) & 127, c16 = q & 3;
                cpasync16(sbase + t * TILE_B + (r * PITCH + c16 * 8) * 2,
                          gsrc[t] + (size_t)r * DM + koff + c16 * 8);
            }
        }
        asm volatile("cp.async.commit_group;");
    };

    issue(0); issue(1); issue(2);

    const int a_r = (lane & 7) + ((lane >> 3) & 1) * 8;
    const int a_c = (lane >> 4) * 8;
    const int b_r = (lane & 7) + ((lane >> 4) & 1) * 8;
    const int b_c = ((lane >> 3) & 1) * 8;

    for (int c = 0; c < NCH; c++) {
        asm volatile("cp.async.wait_group %0;" :: "n"(GSTAGES - 2));
        __syncthreads();
        issue(c + GSTAGES - 1);   // slot (c-1)%4: fully consumed before this barrier

        const uint32_t st = sb + (c % GSTAGES) * STAGE_B;
        const uint32_t sA = st, sB = st + TILE_B;

#pragma unroll
        for (int k16 = 0; k16 < 2; k16++) {
            const int kc = k16 * 16;
            uint32_t ah[4][4], bh[2][4];
#pragma unroll
            for (int mfi = 0; mfi < 4; mfi++)
                ldsm_x4(ah[mfi], sA + ((wm * 64 + mfi * 16 + a_r) * PITCH + kc + a_c) * 2);
#pragma unroll
            for (int nfp = 0; nfp < 2; nfp++)
                ldsm_x4(bh[nfp], sB + ((wn * 32 + nfp * 16 + b_r) * PITCH + kc + b_c) * 2);
#pragma unroll
            for (int mfi = 0; mfi < 4; mfi++)
#pragma unroll
                for (int nf = 0; nf < 4; nf++)
                    mma_f16(acc[mfi][nf], ah[mfi], &bh[nf >> 1][(nf & 1) * 2]);
        }
    }

#pragma unroll
    for (int mfi = 0; mfi < 4; mfi++)
#pragma unroll
        for (int nf = 0; nf < 4; nf++) {
            int row = bm * BM + wm * 64 + mfi * 16 + (lane >> 2);
            int col = bn * BN + wn * 32 + nf * 8 + (lane & 3) * 2;
            float v0 = acc[mfi][nf][0] * scale, v1 = acc[mfi][nf][1] * scale;
            float v2 = acc[mfi][nf][2] * scale, v3 = acc[mfi][nf][3] * scale;
            if (OMODE == 0) {
                *(float2*)&C[(size_t)row * DM + col]       = make_float2(v0, v1);
                *(float2*)&C[(size_t)(row + 8) * DM + col] = make_float2(v2, v3);
            } else {
                *(uint32_t*)&Ch[(size_t)row * DM + col] =
                    pack_h2(__float2half_rn(v0), __float2half_rn(v1));
                *(uint32_t*)&Ch[(size_t)(row + 8) * DM + col] =
                    pack_h2(__float2half_rn(v2), __float2half_rn(v3));
            }
        }
}

__global__ __launch_bounds__(256, 2)
void qkv_mma_kernel()
{
    const int z = blockIdx.z;
    if (z == 0)
        gemm_body<2>(g_x, g_wf[0], nullptr, g_q, ATT_SCALE * LOG2E);
    else if (z == 1)
        gemm_body<2>(g_x, g_wf[1], nullptr, g_k, 1.f);
    else
        gemm_body<2>(g_x, g_wf[2], nullptr, g_v, 1.f);
}
__global__ __launch_bounds__(256, 2)
void out_mma_kernel(float* __restrict__ out)
{
    gemm_body<0>(g_a, g_wf[3], out, nullptr, 1.f);
}

// ---- conversions --------------------------------------------------------------
__global__ __launch_bounds__(256) void conv_x_kernel(const float* __restrict__ s) {
    int i = blockIdx.x * 256 + threadIdx.x;
    float4 v = ((const float4*)s)[i];
    ((uint32_t*)g_x)[i*2+0] = pack_h2(__float2half_rn(v.x), __float2half_rn(v.y));
    ((uint32_t*)g_x)[i*2+1] = pack_h2(__float2half_rn(v.z), __float2half_rn(v.w));
}
__global__ __launch_bounds__(256) void conv_wt_kernel(const float* __restrict__ W0,
                                                      const float* __restrict__ W1,
                                                      const float* __restrict__ W2,
                                                      const float* __restrict__ W3) {
    __shared__ float tile[32][33];
    const int z = blockIdx.z;
    const float* W = (z == 0) ? W0 : (z == 1) ? W1 : (z == 2) ? W2 : W3;
    const int n0 = blockIdx.x * 32, k0 = blockIdx.y * 32;
    const int tx = threadIdx.x, ty = threadIdx.y;
#pragma unroll
    for (int i = ty; i < 32; i += 8)
        tile[i][tx] = W[(size_t)(k0 + i) * DM + n0 + tx];
    __syncthreads();
#pragma unroll
    for (int i = ty; i < 32; i += 8)
        g_wf[z][(size_t)(n0 + i) * DM + k0 + tx] = __float2half_rn(tile[tx][i]);
}

// ---- Flash attention (single-pass QK and PV, base-2 softmax) ---------------------
__global__ __launch_bounds__(256, 2)
void attn_kernel(const unsigned char* __restrict__ pad)
{
    extern __shared__ char smem[];
    const uint32_t sb = smem_to_u32(smem);
    const int tid = threadIdx.x, lane = tid & 31, wq = tid >> 5;
    const int b = blockIdx.y >> 4, h = blockIdx.y & 15;
    const int bx = (gridDim.x - 1) - blockIdx.x;   // heavy blocks first
    const int qbase = bx * 128;
    const int ntiles = bx * 2 + 2;

    // Q load (single operand) — bundled into commit group 0
    {
        const __half* srcq = g_q + (size_t)(b * SEQ + qbase) * DM + h * HD;
#pragma unroll
        for (int i = 0; i < 4; i++) {
            int q = tid + i * 256;
            int row = q >> 3, ch = q & 7;
            cpasync16(sb + AOFF_Q + (row * APITCH + ch * 8) * 2,
                      srcq + (size_t)row * DM + ch * 8);
        }
    }

    auto issue = [&](int t) {
        if (t < ntiles) {
            const int k0 = t * 64;
            const uint32_t sbase = sb + AOFF_ST + (t % ASTAGES) * ASTG_B;
            const __half* gs[2] = {
                g_k + (size_t)(b * SEQ + k0) * DM + h * HD,
                g_v + (size_t)(b * SEQ + k0) * DM + h * HD };
#pragma unroll
            for (int i = 0; i < 4; i++) {
                int q = tid + i * 256;
                int tt = q >> 9, row = (q >> 3) & 63, ch = q & 7;
                cpasync16(sbase + tt * AK_B + (row * APITCH + ch * 8) * 2,
                          gs[tt] + (size_t)row * DM + ch * 8);
            }
        }
        asm volatile("cp.async.commit_group;");
    };
    auto pmload = [&](int t) {
        if (t < ntiles && tid < 64) {
            float v = pad[b * SEQ + t * 64 + tid] ? -CUDART_INF_F : 0.f;
            *(float*)(smem + AOFF_PM + (t % ASTAGES) * 256 + tid * 4) = v;
        }
    };

    pmload(0); issue(0);
    pmload(1); issue(1);

    const int r  = lane >> 2;
    const int c2 = (lane & 3) * 2;
    const int row0 = qbase + wq * 16 + r;
    const int row1 = row0 + 8;
    const int qmax = qbase + wq * 16 + 15;

    const int a_r = (lane & 7) + ((lane >> 3) & 1) * 8;
    const int a_c = (lane >> 4) * 8;
    const int b_r = (lane & 7) + ((lane >> 4) & 1) * 8;
    const int b_c = ((lane >> 3) & 1) * 8;
    const int v_r = (lane & 7) + ((lane >> 3) & 1) * 8;
    const int v_c = (lane >> 4) * 8;

    float m0 = -CUDART_INF_F, m1 = -CUDART_INF_F, l0 = 0.f, l1 = 0.f;
    float o[8][4];
#pragma unroll
    for (int i = 0; i < 8; i++)
#pragma unroll
        for (int j = 0; j < 4; j++) o[i][j] = 0.f;

    uint32_t qf[4][4];

    for (int t = 0; t < ntiles; t++) {
        asm volatile("cp.async.wait_group %0;" :: "n"(1));
        __syncthreads();

        if (t == 0) {
#pragma unroll
            for (int dk = 0; dk < 4; dk++)
                ldsm_x4(qf[dk], sb + AOFF_Q + ((wq * 16 + a_r) * APITCH + dk * 16 + a_c) * 2);
        }
        pmload(t + 2);
        issue(t + 2);

        const int k0 = t * 64;
        if (k0 <= qmax) {
            const uint32_t st = sb + AOFF_ST + (t % ASTAGES) * ASTG_B;
            // ---- S = Q K^T, single-pass fp16 ----
            float s[8][4];
#pragma unroll
            for (int f = 0; f < 8; f++)
#pragma unroll
                for (int j = 0; j < 4; j++) s[f][j] = 0.f;

#pragma unroll
            for (int dk = 0; dk < 4; dk++) {
                uint32_t kf[4][4];
#pragma unroll
                for (int g = 0; g < 4; g++)
                    ldsm_x4(kf[g], st + ((g * 16 + b_r) * APITCH + dk * 16 + b_c) * 2);
#pragma unroll
                for (int f = 0; f < 8; f++)
                    mma_f16(s[f], qf[dk], &kf[f >> 1][(f & 1) * 2]);
            }

            // ---- masks ----
            const bool needc = (k0 + 63 > row0);
#pragma unroll
            for (int f = 0; f < 8; f++) {
                float2 pmv = *(float2*)(smem + AOFF_PM + (t % ASTAGES) * 256 + (f * 8 + c2) * 4);
                s[f][0] += pmv.x; s[f][1] += pmv.y;
                s[f][2] += pmv.x; s[f][3] += pmv.y;
                if (needc) {
                    int k = k0 + f * 8 + c2;
                    if (k     > row0) s[f][0] = -CUDART_INF_F;
                    if (k + 1 > row0) s[f][1] = -CUDART_INF_F;
                    if (k     > row1) s[f][2] = -CUDART_INF_F;
                    if (k + 1 > row1) s[f][3] = -CUDART_INF_F;
                }
            }

            // ---- online softmax (base 2) ----
            float mx0 = -CUDART_INF_F, mx1 = -CUDART_INF_F;
#pragma unroll
            for (int f = 0; f < 8; f++) {
                mx0 = fmaxf(mx0, fmaxf(s[f][0], s[f][1]));
                mx1 = fmaxf(mx1, fmaxf(s[f][2], s[f][3]));
            }
            mx0 = fmaxf(mx0, __shfl_xor_sync(0xffffffff, mx0, 1));
            mx0 = fmaxf(mx0, __shfl_xor_sync(0xffffffff, mx0, 2));
            mx1 = fmaxf(mx1, __shfl_xor_sync(0xffffffff, mx1, 1));
            mx1 = fmaxf(mx1, __shfl_xor_sync(0xffffffff, mx1, 2));
            const float mn0 = fmaxf(m0, mx0), mn1 = fmaxf(m1, mx1);
            const float al0 = exp2f(m0 - mn0), al1 = exp2f(m1 - mn1);
            m0 = mn0; m1 = mn1;

            uint32_t pah[4][4];
            float rs0 = 0.f, rs1 = 0.f;
#pragma unroll
            for (int f = 0; f < 8; f++) {
                float p0 = exp2f(s[f][0] - mn0), p1 = exp2f(s[f][1] - mn0);
                float p2 = exp2f(s[f][2] - mn1), p3 = exp2f(s[f][3] - mn1);
                rs0 += p0 + p1; rs1 += p2 + p3;
                const int ks = f >> 1, hi = (f & 1) * 2;
                pah[ks][hi]     = pack_h2(__float2half_rn(p0), __float2half_rn(p1));
                pah[ks][hi + 1] = pack_h2(__float2half_rn(p2), __float2half_rn(p3));
            }
            rs0 += __shfl_xor_sync(0xffffffff, rs0, 1);
            rs0 += __shfl_xor_sync(0xffffffff, rs0, 2);
            rs1 += __shfl_xor_sync(0xffffffff, rs1, 1);
            rs1 += __shfl_xor_sync(0xffffffff, rs1, 2);
            l0 = l0 * al0 + rs0;
            l1 = l1 * al1 + rs1;

#pragma unroll
            for (int nd = 0; nd < 8; nd++) {
                o[nd][0] *= al0; o[nd][1] *= al0;
                o[nd][2] *= al1; o[nd][3] *= al1;
            }

            // ---- O += P V, single-pass fp16 ----
#pragma unroll
            for (int ks = 0; ks < 4; ks++) {
                uint32_t vf[4][4];
#pragma unroll
                for (int g = 0; g < 4; g++)
                    ldsm_x4_t(vf[g], st + AK_B + ((ks * 16 + v_r) * APITCH + g * 16 + v_c) * 2);
#pragma unroll
                for (int nd = 0; nd < 8; nd++)
                    mma_f16(o[nd], pah[ks], &vf[nd >> 1][(nd & 1) * 2]);
            }
        }
    }

    // ---- epilogue: O/l -> single fp16 into g_a ----
    const float inv0 = (l0 > 0.f) ? (1.f / l0) : 0.f;
    const float inv1 = (l1 > 0.f) ? (1.f / l1) : 0.f;
    const size_t r0off = (size_t)(b * SEQ + row0) * DM + h * HD;
    const size_t r1off = (size_t)(b * SEQ + row1) * DM + h * HD;
#pragma unroll
    for (int nd = 0; nd < 8; nd++) {
        const int col = nd * 8 + c2;
        *(uint32_t*)&g_a[r0off + col] =
            pack_h2(__float2half_rn(o[nd][0] * inv0), __float2half_rn(o[nd][1] * inv0));
        *(uint32_t*)&g_a[r1off + col] =
            pack_h2(__float2half_rn(o[nd][2] * inv1), __float2half_rn(o[nd][3] * inv1));
    }
}

// ---- Launch ------------------------------------------------------------------------
extern "C" void kernel_launch(void* const* d_in, const int* in_sizes, int n_in,
                              void* d_out, int out_size)
{
    (void)in_sizes; (void)n_in; (void)out_size;
    const float*         x   = (const float*)d_in[0];
    const unsigned char* pad = (const unsigned char*)d_in[1];
    const float*         Wq  = (const float*)d_in[2];
    const float*         Wk  = (const float*)d_in[3];
    const float*         Wv  = (const float*)d_in[4];
    const float*         Wo  = (const float*)d_in[5];
    float*               out = (float*)d_out;

    cudaFuncSetAttribute(qkv_mma_kernel, cudaFuncAttributeMaxDynamicSharedMemorySize, GEMM_SMEM);
    cudaFuncSetAttribute(out_mma_kernel, cudaFuncAttributeMaxDynamicSharedMemorySize, GEMM_SMEM);
    cudaFuncSetAttribute(attn_kernel, cudaFuncAttributeMaxDynamicSharedMemorySize, ATTN_SMEM);

    conv_x_kernel<<<MROWS * DM / 4 / 256, 256>>>(x);
    conv_wt_kernel<<<dim3(DM / 32, DM / 32, 4), dim3(32, 8)>>>(Wq, Wk, Wv, Wo);

    qkv_mma_kernel<<<dim3(DM / BN, MROWS / BM, 3), 256, GEMM_SMEM>>>();

    attn_kernel<<<dim3(SEQ / 128, BATCH * NH), 256, ATTN_SMEM>>>(pad);

    out_mma_kernel<<<dim3(DM / BN, MROWS / BM), 256, GEMM_SMEM>>>(out);
}